// round 10
// baseline (speedup 1.0000x reference)
#include <cuda_runtime.h>
#include <math.h>

#define B_    64
#define S_    196
#define DM    1024
#define DI    512
#define MEMN  25
#define ITERS 50
#define OUTN  1000
#define MS    (B_*S_)

#define OFF_CERT (B_*OUTN*ITERS)
#define OFF_SYNC (OFF_CERT + B_*2*ITERS)

// ------------------------- device scratch (no cudaMalloc allowed) ----------
__device__ __align__(16) float g_kv  [MS*DI];
__device__ __align__(16) float g_KV  [MS*DM];
__device__ __align__(16) float g_Wqkv[3*DM*DM];
__device__ __align__(16) float g_Qb  [B_*MEMN*DM];
__device__ __align__(16) float g_Kb  [B_*MEMN*DM];
__device__ __align__(16) float g_vc  [B_*DM];
__device__ __align__(16) float g_st  [MEMN*DM*B_];
__device__ __align__(16) float g_act [B_*DM];
__device__ __align__(16) float g_sync[B_*DM];
__device__ __align__(16) float g_o   [B_*DI];
__device__ __align__(16) float g_pre [B_*(DI+DM)];
__device__ __align__(16) float g_P   [786432];

// ------------------------- reductions --------------------------------------
__device__ __forceinline__ float warpSum(float v){
    #pragma unroll
    for(int o=16;o;o>>=1) v += __shfl_down_sync(0xffffffffu,v,o);
    return v;
}
__device__ __forceinline__ float warpMax(float v){
    #pragma unroll
    for(int o=16;o;o>>=1) v = fmaxf(v,__shfl_down_sync(0xffffffffu,v,o));
    return v;
}
__device__ float blockSum(float v, float* buf){
    int lane=threadIdx.x&31, w=threadIdx.x>>5, nw=(blockDim.x+31)>>5;
    v=warpSum(v);
    if(lane==0) buf[w]=v;
    __syncthreads();
    v=(threadIdx.x<nw)?buf[threadIdx.x]:0.f;
    if(w==0) v=warpSum(v);
    if(threadIdx.x==0) buf[0]=v;
    __syncthreads();
    float r=buf[0]; __syncthreads(); return r;
}
__device__ float blockMax(float v, float* buf){
    int lane=threadIdx.x&31, w=threadIdx.x>>5, nw=(blockDim.x+31)>>5;
    v=warpMax(v);
    if(lane==0) buf[w]=v;
    __syncthreads();
    v=(threadIdx.x<nw)?buf[threadIdx.x]:-1e30f;
    if(w==0) v=warpMax(v);
    if(threadIdx.x==0) buf[0]=v;
    __syncthreads();
    float r=buf[0]; __syncthreads(); return r;
}
__device__ __forceinline__ float sigm(float x){ return 1.f/(1.f+__expf(-x)); }

// ------------------------- generic split-K SGEMM ---------------------------
// P[(z*M+m)*N+n] = sum_{k in chunk z} A[m][k]*W[n][k]  (+bias when given)
__global__ void __launch_bounds__(256) k_gemm(const float* __restrict__ A,
                                              const float* __restrict__ W,
                                              float* __restrict__ P,
                                              const float* __restrict__ bias,
                                              int M,int N,int K,int kchunk){
    __shared__ float As[16][64];
    __shared__ float Ws[16][64];
    const int n0=blockIdx.x*64, m0=blockIdx.y*64, k0=blockIdx.z*kchunk;
    const int tid=threadIdx.x;
    const int tx=tid&15, ty=tid>>4;
    const int lr=tid>>2, lc=tid&3;
    float c[4][4];
    #pragma unroll
    for(int i=0;i<4;i++){c[i][0]=0;c[i][1]=0;c[i][2]=0;c[i][3]=0;}
    const float* Ab = A + (size_t)(m0+lr)*K + k0 + lc*4;
    const bool wok = (n0+lr)<N;
    const float* Wb = W + (size_t)(n0+lr)*K + k0 + lc*4;
    for(int kk=0; kk<kchunk; kk+=16){
        float4 av = *(const float4*)(Ab+kk);
        float4 wv = wok ? *(const float4*)(Wb+kk) : make_float4(0,0,0,0);
        __syncthreads();
        As[lc*4+0][lr]=av.x; As[lc*4+1][lr]=av.y; As[lc*4+2][lr]=av.z; As[lc*4+3][lr]=av.w;
        Ws[lc*4+0][lr]=wv.x; Ws[lc*4+1][lr]=wv.y; Ws[lc*4+2][lr]=wv.z; Ws[lc*4+3][lr]=wv.w;
        __syncthreads();
        #pragma unroll
        for(int q=0;q<16;q++){
            float4 a=*(const float4*)&As[q][ty*4];
            float4 w=*(const float4*)&Ws[q][tx*4];
            c[0][0]+=a.x*w.x; c[0][1]+=a.x*w.y; c[0][2]+=a.x*w.z; c[0][3]+=a.x*w.w;
            c[1][0]+=a.y*w.x; c[1][1]+=a.y*w.y; c[1][2]+=a.y*w.z; c[1][3]+=a.y*w.w;
            c[2][0]+=a.z*w.x; c[2][1]+=a.z*w.y; c[2][2]+=a.z*w.z; c[2][3]+=a.z*w.w;
            c[3][0]+=a.w*w.x; c[3][1]+=a.w*w.y; c[3][2]+=a.w*w.z; c[3][3]+=a.w*w.w;
        }
    }
    float* Pb = P + ((size_t)blockIdx.z*M + m0)*N + n0;
    #pragma unroll
    for(int i=0;i<4;i++){
        int m=ty*4+i;
        #pragma unroll
        for(int j=0;j<4;j++){
            int n=tx*4+j;
            if(n0+n<N){
                float v=c[i][j];
                if(bias) v+=bias[n0+n];
                Pb[(size_t)m*N+n]=v;
            }
        }
    }
}

// ------------------------- setup kernels -----------------------------------
__global__ void k_copyW(const float* __restrict__ wq,const float* __restrict__ wk,
                        const float* __restrict__ wv,float* __restrict__ dst){
    int i=blockIdx.x*blockDim.x+threadIdx.x;
    if(i>=3*DM*DM) return;
    int part=i/(DM*DM), r=i%(DM*DM);
    dst[i]=(part==0)?wq[r]:(part==1)?wk[r]:wv[r];
}
__global__ void k_initact(const float* __restrict__ sas,float* __restrict__ act){
    int i=blockIdx.x*blockDim.x+threadIdx.x;
    if(i<B_*DM) act[i]=sas[i&(DM-1)];
}
__global__ void k_initst(const float* __restrict__ strace,float* __restrict__ st){
    int i=blockIdx.x*blockDim.x+threadIdx.x;
    if(i>=MEMN*DM*B_) return;
    int slot=i/(DM*B_), r=i%(DM*B_), d=r/B_;
    st[i]=strace[d*MEMN+slot];
}
__global__ void k_lnkv(const float* __restrict__ tmp,const float* __restrict__ kvb,
                       const float* __restrict__ lns,const float* __restrict__ lnb,
                       float* __restrict__ kv){
    __shared__ float red[33];
    int r=blockIdx.x, tid=threadIdx.x;
    float v0=tmp[r*DI+tid]+kvb[tid];
    float v1=tmp[r*DI+tid+256]+kvb[tid+256];
    float s=blockSum(v0+v1,red);
    float sq=blockSum(v0*v0+v1*v1,red);
    float mean=s*(1.f/DI);
    float var=sq*(1.f/DI)-mean*mean;
    float rstd=rsqrtf(var+1e-5f);
    kv[r*DI+tid]    =(v0-mean)*rstd*lns[tid]    +lnb[tid];
    kv[r*DI+tid+256]=(v1-mean)*rstd*lns[tid+256]+lnb[tid+256];
}
__global__ void k_scatter(const float* __restrict__ P,float* __restrict__ Qb,
                          float* __restrict__ Kb,float* __restrict__ vc,
                          int slot,int fillAll,int nz){
    int i=blockIdx.x*blockDim.x+threadIdx.x;
    if(i>=B_*3*DM) return;
    int b=i/(3*DM), n=i%(3*DM);
    float v=0.f;
    for(int z=0;z<nz;z++) v+=P[((size_t)z*B_+b)*3*DM+n];
    if(n<DM){
        if(fillAll){ for(int m=0;m<MEMN;m++) Qb[(b*MEMN+m)*DM+n]=v; }
        else Qb[(b*MEMN+slot)*DM+n]=v;
    }else if(n<2*DM){
        int nn=n-DM;
        if(fillAll){ for(int m=0;m<MEMN;m++) Kb[(b*MEMN+m)*DM+nn]=v; }
        else Kb[(b*MEMN+slot)*DM+nn]=v;
    }else vc[b*DM+(n-2*DM)]=v;
}

// ------------------------- sync attention ----------------------------------
__global__ void __launch_bounds__(128) k_sync(const float* __restrict__ Qb,
                                              const float* __restrict__ Kb,
                                              const float* __restrict__ vc,
                                              float* __restrict__ syncv,
                                              float* __restrict__ outOpt){
    __shared__ float Ks[MEMN][128];
    __shared__ float Vs[128];
    int b=blockIdx.x, h=blockIdx.y, d=threadIdx.x;
    float q[MEMN];
    #pragma unroll
    for(int m=0;m<MEMN;m++){
        Ks[m][d]=Kb[(b*MEMN+m)*DM + h*128 + d];
        q[m]    =Qb[(b*MEMN+m)*DM + h*128 + d];
    }
    Vs[d]=vc[b*DM + h*128 + d];
    __syncthreads();
    const float sc=0.08838834764831845f;
    float mx=-1e30f, Z=0.f, acc=0.f;
    for(int e=0;e<128;e+=4){
        float s0=0,s1=0,s2=0,s3=0;
        #pragma unroll
        for(int m=0;m<MEMN;m++){
            float qm=q[m];
            s0+=qm*Ks[m][e]; s1+=qm*Ks[m][e+1]; s2+=qm*Ks[m][e+2]; s3+=qm*Ks[m][e+3];
        }
        s0*=sc; s1*=sc; s2*=sc; s3*=sc;
        float m2=fmaxf(mx,fmaxf(fmaxf(s0,s1),fmaxf(s2,s3)));
        float cc=__expf(mx-m2);
        float e0=__expf(s0-m2),e1=__expf(s1-m2),e2=__expf(s2-m2),e3=__expf(s3-m2);
        Z  = Z*cc + e0+e1+e2+e3;
        acc= acc*cc + e0*Vs[e]+e1*Vs[e+1]+e2*Vs[e+2]+e3*Vs[e+3];
        mx=m2;
    }
    float att=acc/Z;
    syncv[b*DM + d*8 + h]=att;
    if(outOpt) outOpt[b*DM + d*8 + h]=att;
}

// ------------------------- cross attention ---------------------------------
__global__ void __launch_bounds__(256) k_cross(const float* __restrict__ P,
                                               const float* __restrict__ qb,
                                               const float* __restrict__ inw,
                                               const float* __restrict__ inb,
                                               const float* __restrict__ KV,
                                               float* __restrict__ o){
    __shared__ float qs[DI];
    __shared__ float q2[64];
    __shared__ float ws[196];
    __shared__ float os[4][64];
    __shared__ float red[33];
    int b=blockIdx.x, h=blockIdx.y, tid=threadIdx.x;
    for(int j=tid;j<DI;j+=256){
        float v=qb[j];
        for(int z=0;z<8;z++) v+=P[((size_t)z*B_+b)*DI+j];
        qs[j]=v;
    }
    __syncthreads();
    if(tid<64){
        const float* wr=inw+(size_t)(h*64+tid)*DI;
        float a=inb[h*64+tid];
        for(int j=0;j<DI;j++) a+=wr[j]*qs[j];
        q2[tid]=a;
    }
    __syncthreads();
    float sv=-1e30f;
    if(tid<S_){
        const float* kr=KV+((size_t)(b*S_+tid))*DM + h*64;
        float a=0.f;
        #pragma unroll 8
        for(int dd=0;dd<64;dd++) a+=q2[dd]*kr[dd];
        sv=a*0.125f;
    }
    float mxv=blockMax(sv,red);
    float ev=(tid<S_)?__expf(sv-mxv):0.f;
    float Z=blockSum(ev,red);
    if(tid<S_) ws[tid]=ev/Z;
    __syncthreads();
    int dd=tid&63, part=tid>>6;
    float acc=0.f;
    for(int s=part*49;s<part*49+49;s++)
        acc+=ws[s]*KV[((size_t)(b*S_+s))*DM + DI + h*64 + dd];
    os[part][dd]=acc;
    __syncthreads();
    if(tid<64)
        o[b*DI + h*64 + tid]=os[0][tid]+os[1][tid]+os[2][tid]+os[3][tid];
}

__global__ void k_pre(const float* __restrict__ P,const float* __restrict__ opb,
                      const float* __restrict__ act,float* __restrict__ pre){
    int i=blockIdx.x*blockDim.x+threadIdx.x;
    if(i>=B_*(DI+DM)) return;
    int b=i/(DI+DM), n=i%(DI+DM);
    float v;
    if(n<DI){
        v=opb[n];
        for(int z=0;z<4;z++) v+=P[((size_t)z*B_+b)*DI+n];
    }else v=act[b*DM+(n-DI)];
    pre[i]=v;
}

__global__ void __launch_bounds__(256) k_synep(const float* __restrict__ P,
                                               const float* __restrict__ sb,
                                               const float* __restrict__ lns,
                                               const float* __restrict__ lnb,
                                               float* __restrict__ st,int w){
    __shared__ float vals[DM];
    __shared__ float red[33];
    int b=blockIdx.x, tid=threadIdx.x;
    float s=0.f, sq=0.f;
    for(int r=0;r<4;r++){
        int j=tid+r*256;
        float a=sb[j], g=sb[DM+j];
        for(int z=0;z<6;z++){
            a+=P[((size_t)z*B_+b)*2048 + j];
            g+=P[((size_t)z*B_+b)*2048 + DM + j];
        }
        float v=a*sigm(g);
        vals[j]=v; s+=v; sq+=v*v;
    }
    s=blockSum(s,red); sq=blockSum(sq,red);
    float mean=s*(1.f/DM);
    float var=sq*(1.f/DM)-mean*mean;
    float rstd=rsqrtf(var+1e-5f);
    for(int r=0;r<4;r++){
        int j=tid+r*256;
        st[((size_t)w*DM + j)*B_ + b]=(vals[j]-mean)*rstd*lns[j]+lnb[j];
    }
}

__global__ void __launch_bounds__(256) k_nlm(const float* __restrict__ st,
                                             const float* __restrict__ w1,
                                             const float* __restrict__ b1,
                                             const float* __restrict__ w2,
                                             const float* __restrict__ b2,
                                             float* __restrict__ act,int t){
    __shared__ float w1s[MEMN*32*4];
    __shared__ float b1s[32*4];
    __shared__ float w2s[32*4];
    __shared__ float b2s[8];
    int tid=threadIdx.x, d0=blockIdx.x*4;
    for(int i=tid;i<MEMN*32*4;i+=256){
        int m=i>>7, r=i&127, j=r>>2, dl=r&3;
        w1s[i]=w1[(size_t)(m*32+j)*DM + d0+dl];
    }
    if(tid<128){ int j=tid>>2, dl=tid&3; b1s[tid]=b1[(d0+dl)*32+j]; }
    else {
        int i=tid-128; int hh=i>>3, o=(i>>2)&1, dl=i&3;
        w2s[i]=w2[(size_t)(hh*2+o)*DM + d0+dl];
    }
    if(tid<8){ int o=tid>>2, dl=tid&3; b2s[tid]=b2[(d0+dl)*2+o]; }
    __syncthreads();
    int b=tid&63, dl=tid>>6, d=d0+dl;
    float stv[MEMN];
    #pragma unroll
    for(int m=0;m<MEMN;m++){
        int phys=(t+1+m)%MEMN;
        stv[m]=st[((size_t)phys*DM + d)*B_ + b];
    }
    float o0=0.f,o1=0.f;
    #pragma unroll
    for(int j=0;j<16;j++){
        float a=b1s[j*4+dl], g=b1s[(j+16)*4+dl];
        #pragma unroll
        for(int m=0;m<MEMN;m++){
            a+=stv[m]*w1s[(m*32+j)*4+dl];
            g+=stv[m]*w1s[(m*32+j+16)*4+dl];
        }
        float hv=a*sigm(g);
        o0+=hv*w2s[(j*2+0)*4+dl];
        o1+=hv*w2s[(j*2+1)*4+dl];
    }
    o0+=b2s[0*4+dl]; o1+=b2s[1*4+dl];
    act[b*DM+d]=o0*sigm(o1);
}

__global__ void __launch_bounds__(256) k_pred(const float* __restrict__ P,
                                              const float* __restrict__ ob,
                                              float* __restrict__ out,int t){
    __shared__ float pv[OUTN];
    __shared__ float red[33];
    int b=blockIdx.x, tid=threadIdx.x;
    float lmax=-1e30f;
    for(int j=tid;j<OUTN;j+=256){
        float v=ob[j];
        for(int z=0;z<4;z++) v+=P[((size_t)z*B_+b)*OUTN+j];
        pv[j]=v;
        out[((size_t)b*OUTN+j)*ITERS+t]=v;
        lmax=fmaxf(lmax,v);
    }
    float mx=blockMax(lmax,red);
    float lz=0.f, ls1=0.f;
    for(int j=tid;j<OUTN;j+=256){
        float e=__expf(pv[j]-mx);
        lz+=e; ls1+=e*pv[j];
    }
    float Z=blockSum(lz,red);
    float S1=blockSum(ls1,red);
    if(tid==0){
        float logZ=logf(Z);
        float plogp=S1/Z - mx - logZ;
        float ne=-plogp*(1.f/logf((float)OUTN));
        out[OFF_CERT + ((size_t)b*2+0)*ITERS + t]=ne;
        out[OFF_CERT + ((size_t)b*2+1)*ITERS + t]=1.f-ne;
    }
}

// ------------------------- host driver -------------------------------------
extern "C" void kernel_launch(void* const* d_in, const int* in_sizes, int n_in,
                              void* d_out, int out_size){
    (void)in_sizes; (void)n_in; (void)out_size;
    const float* x    =(const float*)d_in[0];
    const float* kv_w =(const float*)d_in[1];
    const float* kv_b =(const float*)d_in[2];
    const float* lnks =(const float*)d_in[3];
    const float* lnkb =(const float*)d_in[4];
    const float* q_w  =(const float*)d_in[5];
    const float* q_b  =(const float*)d_in[6];
    const float* inw  =(const float*)d_in[7];
    const float* inb  =(const float*)d_in[8];
    const float* opw  =(const float*)d_in[9];
    const float* opb  =(const float*)d_in[10];
    const float* Wq   =(const float*)d_in[11];
    const float* Wk   =(const float*)d_in[12];
    const float* Wv   =(const float*)d_in[13];
    const float* synw =(const float*)d_in[14];
    const float* synb =(const float*)d_in[15];
    const float* slns =(const float*)d_in[16];
    const float* slnb =(const float*)d_in[17];
    const float* w1   =(const float*)d_in[18];
    const float* b1   =(const float*)d_in[19];
    const float* w2   =(const float*)d_in[20];
    const float* b2   =(const float*)d_in[21];
    const float* sas  =(const float*)d_in[22];
    const float* strc =(const float*)d_in[23];
    const float* outw =(const float*)d_in[24];
    const float* outb =(const float*)d_in[25];
    float* out=(float*)d_out;

    float *p_kv,*p_KV,*p_W,*p_Qb,*p_Kb,*p_vc,*p_st,*p_act,*p_sync,*p_o,*p_pre,*p_P;
    cudaGetSymbolAddress((void**)&p_kv,  g_kv);
    cudaGetSymbolAddress((void**)&p_KV,  g_KV);
    cudaGetSymbolAddress((void**)&p_W,   g_Wqkv);
    cudaGetSymbolAddress((void**)&p_Qb,  g_Qb);
    cudaGetSymbolAddress((void**)&p_Kb,  g_Kb);
    cudaGetSymbolAddress((void**)&p_vc,  g_vc);
    cudaGetSymbolAddress((void**)&p_st,  g_st);
    cudaGetSymbolAddress((void**)&p_act, g_act);
    cudaGetSymbolAddress((void**)&p_sync,g_sync);
    cudaGetSymbolAddress((void**)&p_o,   g_o);
    cudaGetSymbolAddress((void**)&p_pre, g_pre);
    cudaGetSymbolAddress((void**)&p_P,   g_P);

    // ---- setup ----
    k_copyW<<<(3*DM*DM+255)/256,256>>>(Wq,Wk,Wv,p_W);
    k_initact<<<(B_*DM+255)/256,256>>>(sas,p_act);
    k_initst<<<(MEMN*DM*B_+255)/256,256>>>(strc,p_st);
    k_gemm<<<dim3(DI/64,MS/64,1),256>>>(x,kv_w,p_KV,nullptr,MS,DI,DI,DI);
    k_lnkv<<<MS,256>>>(p_KV,kv_b,lnks,lnkb,p_kv);
    k_gemm<<<dim3(DM/64,MS/64,1),256>>>(p_kv,inw+(size_t)DI*DI,p_KV,inb+DI,MS,DM,DI,DI);
    k_gemm<<<dim3(3*DM/64,1,4),256>>>(p_act,p_W,p_P,nullptr,B_,3*DM,DM,256);
    k_scatter<<<(B_*3*DM+255)/256,256>>>(p_P,p_Qb,p_Kb,p_vc,0,1,4);
    k_sync<<<dim3(B_,8),128>>>(p_Qb,p_Kb,p_vc,p_sync,nullptr);

    // ---- 50 thought ticks ----
    for(int t=0;t<ITERS;t++){
        k_gemm<<<dim3(DI/64,1,8),256>>>(p_sync,q_w,p_P,nullptr,B_,DI,DM,128);
        k_cross<<<dim3(B_,8),256>>>(p_P,q_b,inw,inb,p_KV,p_o);
        k_gemm<<<dim3(DI/64,1,4),256>>>(p_o,opw,p_P,nullptr,B_,DI,DI,128);
        k_pre<<<(B_*(DI+DM)+255)/256,256>>>(p_P,opb,p_act,p_pre);
        k_gemm<<<dim3(2048/64,1,6),256>>>(p_pre,synw,p_P,nullptr,B_,2048,DI+DM,256);
        k_synep<<<B_,256>>>(p_P,synb,slns,slnb,p_st,t%MEMN);
        k_nlm<<<DM/4,256>>>(p_st,w1,b1,w2,b2,p_act,t);
        k_gemm<<<dim3(3*DM/64,1,4),256>>>(p_act,p_W,p_P,nullptr,B_,3*DM,DM,256);
        k_scatter<<<(B_*3*DM+255)/256,256>>>(p_P,p_Qb,p_Kb,p_vc,t%MEMN,0,4);
        k_sync<<<dim3(B_,8),128>>>(p_Qb,p_Kb,p_vc,p_sync,
                                   (t==ITERS-1)?(out+OFF_SYNC):nullptr);
        k_gemm<<<dim3((OUTN+63)/64,1,4),256>>>(p_sync,outw,p_P,nullptr,B_,OUTN,DM,256);
        k_pred<<<B_,256>>>(p_P,outb,out,t);
    }
}

// round 11
// speedup vs baseline: 1.1347x; 1.1347x over previous
#include <cuda_runtime.h>
#include <math.h>

#define B_    64
#define S_    196
#define DM    1024
#define DI    512
#define MEMN  25
#define ITERS 50
#define OUTN  1000
#define MS    (B_*S_)

#define OFF_CERT (B_*OUTN*ITERS)
#define OFF_SYNC (OFF_CERT + B_*2*ITERS)

// ------------------------- device scratch ----------------------------------
__device__ __align__(16) float g_kv   [MS*DI];
__device__ __align__(16) float g_KV   [MS*DM];
__device__ __align__(16) float g_Wqkv [3*DM*DM];
__device__ __align__(16) float g_MqT  [DM*DI];        // (wq_c@q_w)^T : [n(1024)][m(512)]
__device__ __align__(16) float g_beff [DI];
__device__ __align__(16) float g_synw2[2048*1536];    // folded synapse weight (2048 x 1536)
__device__ __align__(16) float g_bsyn [2048];
__device__ __align__(16) float g_Qb   [B_*MEMN*DM];
__device__ __align__(16) float g_Kb   [B_*MEMN*DM];
__device__ __align__(16) float g_st   [MEMN*DM*B_];
__device__ __align__(16) float g_act  [B_*DM];
__device__ __align__(16) float g_sync [B_*DM];
__device__ __align__(16) float g_pre2 [B_*1536];      // [o | act]
__device__ __align__(16) float g_P    [3145728];      // split-K partials (24*64*2048)

// ------------------------- reductions --------------------------------------
__device__ __forceinline__ float warpSum(float v){
    #pragma unroll
    for(int o=16;o;o>>=1) v += __shfl_down_sync(0xffffffffu,v,o);
    return v;
}
__device__ __forceinline__ float warpMax(float v){
    #pragma unroll
    for(int o=16;o;o>>=1) v = fmaxf(v,__shfl_down_sync(0xffffffffu,v,o));
    return v;
}
__device__ float blockSum(float v, float* buf){
    int lane=threadIdx.x&31, w=threadIdx.x>>5, nw=(blockDim.x+31)>>5;
    v=warpSum(v);
    if(lane==0) buf[w]=v;
    __syncthreads();
    v=(threadIdx.x<nw)?buf[threadIdx.x]:0.f;
    if(w==0) v=warpSum(v);
    if(threadIdx.x==0) buf[0]=v;
    __syncthreads();
    float r=buf[0]; __syncthreads(); return r;
}
__device__ float blockMax(float v, float* buf){
    int lane=threadIdx.x&31, w=threadIdx.x>>5, nw=(blockDim.x+31)>>5;
    v=warpMax(v);
    if(lane==0) buf[w]=v;
    __syncthreads();
    v=(threadIdx.x<nw)?buf[threadIdx.x]:-1e30f;
    if(w==0) v=warpMax(v);
    if(threadIdx.x==0) buf[0]=v;
    __syncthreads();
    float r=buf[0]; __syncthreads(); return r;
}
__device__ __forceinline__ float sigm(float x){ return 1.f/(1.f+__expf(-x)); }

// ------------------------- split-K SGEMM (A rm MxK, W rm NxK) --------------
// P[(z*M+m)*N+n] = sum_{k in chunk z} A[m][k]*W[n][k] (+bias)
__global__ void __launch_bounds__(256) k_gemm(const float* __restrict__ A,
                                              const float* __restrict__ W,
                                              float* __restrict__ P,
                                              const float* __restrict__ bias,
                                              int M,int N,int K,int kchunk){
    __shared__ float As[16][64];
    __shared__ float Ws[16][64];
    const int n0=blockIdx.x*64, m0=blockIdx.y*64, k0=blockIdx.z*kchunk;
    const int tid=threadIdx.x;
    const int tx=tid&15, ty=tid>>4;
    const int lr=tid>>2, lc=tid&3;
    float c[4][4];
    #pragma unroll
    for(int i=0;i<4;i++){c[i][0]=0;c[i][1]=0;c[i][2]=0;c[i][3]=0;}
    const float* Ab = A + (size_t)(m0+lr)*K + k0 + lc*4;
    const bool wok = (n0+lr)<N;
    const float* Wb = W + (size_t)(n0+lr)*K + k0 + lc*4;
    for(int kk=0; kk<kchunk; kk+=16){
        float4 av = *(const float4*)(Ab+kk);
        float4 wv = wok ? *(const float4*)(Wb+kk) : make_float4(0,0,0,0);
        __syncthreads();
        As[lc*4+0][lr]=av.x; As[lc*4+1][lr]=av.y; As[lc*4+2][lr]=av.z; As[lc*4+3][lr]=av.w;
        Ws[lc*4+0][lr]=wv.x; Ws[lc*4+1][lr]=wv.y; Ws[lc*4+2][lr]=wv.z; Ws[lc*4+3][lr]=wv.w;
        __syncthreads();
        #pragma unroll
        for(int q=0;q<16;q++){
            float4 a=*(const float4*)&As[q][ty*4];
            float4 w=*(const float4*)&Ws[q][tx*4];
            c[0][0]+=a.x*w.x; c[0][1]+=a.x*w.y; c[0][2]+=a.x*w.z; c[0][3]+=a.x*w.w;
            c[1][0]+=a.y*w.x; c[1][1]+=a.y*w.y; c[1][2]+=a.y*w.z; c[1][3]+=a.y*w.w;
            c[2][0]+=a.z*w.x; c[2][1]+=a.z*w.y; c[2][2]+=a.z*w.z; c[2][3]+=a.z*w.w;
            c[3][0]+=a.w*w.x; c[3][1]+=a.w*w.y; c[3][2]+=a.w*w.z; c[3][3]+=a.w*w.w;
        }
    }
    float* Pb = P + ((size_t)blockIdx.z*M + m0)*N + n0;
    #pragma unroll
    for(int i=0;i<4;i++){
        int m=ty*4+i;
        #pragma unroll
        for(int j=0;j<4;j++){
            int n=tx*4+j;
            if(n0+n<N){
                float v=c[i][j];
                if(bias) v+=bias[n0+n];
                Pb[(size_t)m*N+n]=v;
            }
        }
    }
}

// ------------------------- TN GEMM: C = A(MxK,rm,lda) @ B(KxN,rm,ldb) ------
// transC=0: C[m*ldc+n] ; transC=1: C[n*ldc+m]. M,N multiples of 64, K of 16.
__global__ void __launch_bounds__(256) k_gemm_tn(const float* __restrict__ A,
                                                 const float* __restrict__ B,
                                                 float* __restrict__ C,
                                                 int lda,int ldb,int ldc,int K,int transC){
    __shared__ float As[16][64];
    __shared__ float Bs[16][64];
    const int n0=blockIdx.x*64, m0=blockIdx.y*64;
    const int tid=threadIdx.x;
    const int tx=tid&15, ty=tid>>4;
    const int lr=tid>>2, lc=tid&3;
    const int br=tid>>4, bc=(tid&15)*4;
    float c[4][4];
    #pragma unroll
    for(int i=0;i<4;i++){c[i][0]=0;c[i][1]=0;c[i][2]=0;c[i][3]=0;}
    for(int k0=0;k0<K;k0+=16){
        float4 av=*(const float4*)(A+(size_t)(m0+lr)*lda + k0 + lc*4);
        float4 bv=*(const float4*)(B+(size_t)(k0+br)*ldb + n0 + bc);
        __syncthreads();
        As[lc*4+0][lr]=av.x; As[lc*4+1][lr]=av.y; As[lc*4+2][lr]=av.z; As[lc*4+3][lr]=av.w;
        *(float4*)&Bs[br][bc]=bv;
        __syncthreads();
        #pragma unroll
        for(int q=0;q<16;q++){
            float4 a=*(const float4*)&As[q][ty*4];
            float4 w=*(const float4*)&Bs[q][tx*4];
            c[0][0]+=a.x*w.x; c[0][1]+=a.x*w.y; c[0][2]+=a.x*w.z; c[0][3]+=a.x*w.w;
            c[1][0]+=a.y*w.x; c[1][1]+=a.y*w.y; c[1][2]+=a.y*w.z; c[1][3]+=a.y*w.w;
            c[2][0]+=a.z*w.x; c[2][1]+=a.z*w.y; c[2][2]+=a.z*w.z; c[2][3]+=a.z*w.w;
            c[3][0]+=a.w*w.x; c[3][1]+=a.w*w.y; c[3][2]+=a.w*w.z; c[3][3]+=a.w*w.w;
        }
    }
    #pragma unroll
    for(int i=0;i<4;i++){
        #pragma unroll
        for(int j=0;j<4;j++){
            int m=m0+ty*4+i, n=n0+tx*4+j;
            if(transC) C[(size_t)n*ldc+m]=c[i][j];
            else       C[(size_t)m*ldc+n]=c[i][j];
        }
    }
}

// ------------------------- setup kernels -----------------------------------
__global__ void k_copyW(const float* __restrict__ wq,const float* __restrict__ wk,
                        const float* __restrict__ wv,float* __restrict__ dst){
    int i=blockIdx.x*blockDim.x+threadIdx.x;
    if(i>=3*DM*DM) return;
    int part=i/(DM*DM), r=i%(DM*DM);
    dst[i]=(part==0)?wq[r]:(part==1)?wk[r]:wv[r];
}
__global__ void k_copyW2(const float* __restrict__ synw,float* __restrict__ dst){
    int i=blockIdx.x*blockDim.x+threadIdx.x;
    if(i>=2048*1024) return;
    int m=i>>10, k=i&1023;
    dst[(size_t)m*1536+512+k]=synw[(size_t)m*1536+512+k];
}
__global__ void k_initact(const float* __restrict__ sas,float* __restrict__ act,
                          float* __restrict__ pre2){
    int i=blockIdx.x*blockDim.x+threadIdx.x;
    if(i>=B_*DM) return;
    float v=sas[i&(DM-1)];
    act[i]=v;
    pre2[(size_t)(i>>10)*1536 + 512 + (i&(DM-1))]=v;
}
__global__ void k_initst(const float* __restrict__ strace,float* __restrict__ st){
    int i=blockIdx.x*blockDim.x+threadIdx.x;
    if(i>=MEMN*DM*B_) return;
    int slot=i/(DM*B_), r=i%(DM*B_), d=r/B_;
    st[i]=strace[d*MEMN+slot];
}
__global__ void k_lnkv(const float* __restrict__ tmp,const float* __restrict__ kvb,
                       const float* __restrict__ lns,const float* __restrict__ lnb,
                       float* __restrict__ kv){
    __shared__ float red[33];
    int r=blockIdx.x, tid=threadIdx.x;
    float v0=tmp[r*DI+tid]+kvb[tid];
    float v1=tmp[r*DI+tid+256]+kvb[tid+256];
    float s=blockSum(v0+v1,red);
    float sq=blockSum(v0*v0+v1*v1,red);
    float mean=s*(1.f/DI);
    float var=sq*(1.f/DI)-mean*mean;
    float rstd=rsqrtf(var+1e-5f);
    kv[r*DI+tid]    =(v0-mean)*rstd*lns[tid]    +lnb[tid];
    kv[r*DI+tid+256]=(v1-mean)*rstd*lns[tid+256]+lnb[tid+256];
}
// out[i] = b0[i] + dot(W[i,0:K] (row stride lda), v)
__global__ void k_bvec(const float* __restrict__ W,int lda,int K,
                       const float* __restrict__ v,const float* __restrict__ b0,
                       float* __restrict__ o,int n){
    int i=blockIdx.x*blockDim.x+threadIdx.x;
    if(i>=n) return;
    float a=b0[i];
    const float* wr=W+(size_t)i*lda;
    for(int k=0;k<K;k++) a+=wr[k]*v[k];
    o[i]=a;
}

// ------------------------- sync attention (+ring update) -------------------
__global__ void __launch_bounds__(128) k_sync(const float* __restrict__ P,
                                              float* __restrict__ Qb,
                                              float* __restrict__ Kb,
                                              float* __restrict__ syncv,
                                              float* __restrict__ outOpt,
                                              int slot,int fillAll,int nz){
    __shared__ float Ks[MEMN][128];
    __shared__ float Vs[128];
    int b=blockIdx.x, h=blockIdx.y, d=threadIdx.x;
    int col=h*128+d;
    float nq=0.f,nk=0.f,nv=0.f;
    const float* row = P + (size_t)b*3072 + col;
    for(int z=0;z<nz;z++){
        nq += row[0];
        nk += row[1024];
        nv += row[2048];
        row += (size_t)64*3072;
    }
    float q[MEMN];
    if(fillAll){
        #pragma unroll
        for(int m=0;m<MEMN;m++){
            Qb[(b*MEMN+m)*DM+col]=nq;
            Kb[(b*MEMN+m)*DM+col]=nk;
            q[m]=nq; Ks[m][d]=nk;
        }
    }else{
        Qb[(b*MEMN+slot)*DM+col]=nq;
        Kb[(b*MEMN+slot)*DM+col]=nk;
        #pragma unroll
        for(int m=0;m<MEMN;m++){
            q[m]    =(m==slot)?nq:Qb[(b*MEMN+m)*DM+col];
            Ks[m][d]=(m==slot)?nk:Kb[(b*MEMN+m)*DM+col];
        }
    }
    Vs[d]=nv;
    __syncthreads();
    const float sc=0.08838834764831845f;   // 1/sqrt(128)
    float mx=-1e30f, Z=0.f, acc=0.f;
    for(int e=0;e<128;e+=4){
        float s0=0,s1=0,s2=0,s3=0;
        #pragma unroll
        for(int m=0;m<MEMN;m++){
            float qm=q[m];
            s0+=qm*Ks[m][e]; s1+=qm*Ks[m][e+1]; s2+=qm*Ks[m][e+2]; s3+=qm*Ks[m][e+3];
        }
        s0*=sc; s1*=sc; s2*=sc; s3*=sc;
        float m2=fmaxf(mx,fmaxf(fmaxf(s0,s1),fmaxf(s2,s3)));
        float cc=__expf(mx-m2);
        float e0=__expf(s0-m2),e1=__expf(s1-m2),e2=__expf(s2-m2),e3=__expf(s3-m2);
        Z  = Z*cc + e0+e1+e2+e3;
        acc= acc*cc + e0*Vs[e]+e1*Vs[e+1]+e2*Vs[e+2]+e3*Vs[e+3];
        mx=m2;
    }
    float att=acc/Z;
    syncv[b*DM + d*8 + h]=att;
    if(outOpt) outOpt[b*DM + d*8 + h]=att;
}

// ------------------------- cross attention (q2 from folded MqT) ------------
__global__ void __launch_bounds__(256) k_cross(const float* __restrict__ MqT,
                                               const float* __restrict__ beff,
                                               const float* __restrict__ syncv,
                                               const float* __restrict__ KV,
                                               float* __restrict__ pre2){
    __shared__ float ss[DM];
    __shared__ float q2p[4][64];
    __shared__ float q2s[64];
    __shared__ float ws[196];
    __shared__ float os[4][64];
    __shared__ float red[33];
    int b=blockIdx.x, h=blockIdx.y, tid=threadIdx.x;
    for(int j=tid;j<DM;j+=256) ss[j]=syncv[b*DM+j];
    __syncthreads();
    int j=tid&63, part=tid>>6;
    {
        const float* mr = MqT + (size_t)(part*256)*DI + h*64 + j;
        const float* sp = ss + part*256;
        float a=0.f;
        #pragma unroll 8
        for(int k=0;k<256;k++) a += mr[(size_t)k*DI]*sp[k];
        q2p[part][j]=a;
    }
    __syncthreads();
    if(tid<64) q2s[tid]=q2p[0][tid]+q2p[1][tid]+q2p[2][tid]+q2p[3][tid]+beff[h*64+tid];
    __syncthreads();
    float sv=-1e30f;
    if(tid<S_){
        const float* kr=KV+((size_t)(b*S_+tid))*DM + h*64;
        float a=0.f;
        #pragma unroll 8
        for(int dd=0;dd<64;dd++) a+=q2s[dd]*kr[dd];
        sv=a*0.125f;
    }
    float mxv=blockMax(sv,red);
    float ev=(tid<S_)?__expf(sv-mxv):0.f;
    float Z=blockSum(ev,red);
    if(tid<S_) ws[tid]=ev/Z;
    __syncthreads();
    int dd=tid&63;
    float acc=0.f;
    for(int s=part*49;s<part*49+49;s++)
        acc+=ws[s]*KV[((size_t)(b*S_+s))*DM + DI + h*64 + dd];
    os[part][dd]=acc;
    __syncthreads();
    if(tid<64)
        pre2[(size_t)b*1536 + h*64 + tid]=os[0][tid]+os[1][tid]+os[2][tid]+os[3][tid];
}

// ------------------------- synapse epilogue: GLU+LN -> trace slot ----------
__global__ void __launch_bounds__(256) k_synep(const float* __restrict__ P,
                                               const float* __restrict__ sb,
                                               const float* __restrict__ lns,
                                               const float* __restrict__ lnb,
                                               float* __restrict__ st,int w,int nz){
    __shared__ float vals[DM];
    __shared__ float red[33];
    int b=blockIdx.x, tid=threadIdx.x;
    float s=0.f, sq=0.f;
    for(int r=0;r<4;r++){
        int j=tid+r*256;
        float a=sb[j], g=sb[DM+j];
        const float* p = P + (size_t)b*2048 + j;
        for(int z=0;z<nz;z++){
            a+=p[0]; g+=p[DM];
            p += (size_t)64*2048;
        }
        float v=a*sigm(g);
        vals[j]=v; s+=v; sq+=v*v;
    }
    s=blockSum(s,red); sq=blockSum(sq,red);
    float mean=s*(1.f/DM);
    float var=sq*(1.f/DM)-mean*mean;
    float rstd=rsqrtf(var+1e-5f);
    for(int r=0;r<4;r++){
        int j=tid+r*256;
        st[((size_t)w*DM + j)*B_ + b]=(vals[j]-mean)*rstd*lns[j]+lnb[j];
    }
}

// ------------------------- per-neuron NLM ----------------------------------
__global__ void __launch_bounds__(256) k_nlm(const float* __restrict__ st,
                                             const float* __restrict__ w1,
                                             const float* __restrict__ b1,
                                             const float* __restrict__ w2,
                                             const float* __restrict__ b2,
                                             float* __restrict__ act,
                                             float* __restrict__ pre2,int t){
    __shared__ float w1s[MEMN*32*4];
    __shared__ float b1s[32*4];
    __shared__ float w2s[32*4];
    __shared__ float b2s[8];
    int tid=threadIdx.x, d0=blockIdx.x*4;
    for(int i=tid;i<MEMN*32*4;i+=256){
        int m=i>>7, r=i&127, j=r>>2, dl=r&3;
        w1s[i]=w1[(size_t)(m*32+j)*DM + d0+dl];
    }
    if(tid<128){ int j=tid>>2, dl=tid&3; b1s[tid]=b1[(d0+dl)*32+j]; }
    else {
        int i=tid-128; int hh=i>>3, o=(i>>2)&1, dl=i&3;
        w2s[i]=w2[(size_t)(hh*2+o)*DM + d0+dl];
    }
    if(tid<8){ int o=tid>>2, dl=tid&3; b2s[tid]=b2[(d0+dl)*2+o]; }
    __syncthreads();
    int b=tid&63, dl=tid>>6, d=d0+dl;
    float stv[MEMN];
    #pragma unroll
    for(int m=0;m<MEMN;m++){
        int phys=(t+1+m)%MEMN;
        stv[m]=st[((size_t)phys*DM + d)*B_ + b];
    }
    float o0=0.f,o1=0.f;
    #pragma unroll
    for(int j=0;j<16;j++){
        float a=b1s[j*4+dl], g=b1s[(j+16)*4+dl];
        #pragma unroll
        for(int m=0;m<MEMN;m++){
            a+=stv[m]*w1s[(m*32+j)*4+dl];
            g+=stv[m]*w1s[(m*32+j+16)*4+dl];
        }
        float hv=a*sigm(g);
        o0+=hv*w2s[(j*2+0)*4+dl];
        o1+=hv*w2s[(j*2+1)*4+dl];
    }
    o0+=b2s[0*4+dl]; o1+=b2s[1*4+dl];
    float v=o0*sigm(o1);
    act[b*DM+d]=v;
    pre2[(size_t)b*1536 + 512 + d]=v;
}

// ------------------------- output head + certainty -------------------------
__global__ void __launch_bounds__(256) k_pred(const float* __restrict__ P,
                                              const float* __restrict__ ob,
                                              float* __restrict__ out,int t,int nz){
    __shared__ float pv[OUTN];
    __shared__ float red[33];
    int b=blockIdx.x, tid=threadIdx.x;
    float lmax=-1e30f;
    for(int j=tid;j<OUTN;j+=256){
        float v=ob[j];
        const float* p = P + (size_t)b*OUTN + j;
        for(int z=0;z<nz;z++){ v+=p[0]; p+=(size_t)64*OUTN; }
        pv[j]=v;
        out[((size_t)b*OUTN+j)*ITERS+t]=v;
        lmax=fmaxf(lmax,v);
    }
    float mx=blockMax(lmax,red);
    float lz=0.f, ls1=0.f;
    for(int j=tid;j<OUTN;j+=256){
        float e=__expf(pv[j]-mx);
        lz+=e; ls1+=e*pv[j];
    }
    float Z=blockSum(lz,red);
    float S1=blockSum(ls1,red);
    if(tid==0){
        float logZ=logf(Z);
        float plogp=S1/Z - mx - logZ;
        float ne=-plogp*(1.f/logf((float)OUTN));
        out[OFF_CERT + ((size_t)b*2+0)*ITERS + t]=ne;
        out[OFF_CERT + ((size_t)b*2+1)*ITERS + t]=1.f-ne;
    }
}

// ------------------------- host driver -------------------------------------
extern "C" void kernel_launch(void* const* d_in, const int* in_sizes, int n_in,
                              void* d_out, int out_size){
    (void)in_sizes; (void)n_in; (void)out_size;
    const float* x    =(const float*)d_in[0];
    const float* kv_w =(const float*)d_in[1];
    const float* kv_b =(const float*)d_in[2];
    const float* lnks =(const float*)d_in[3];
    const float* lnkb =(const float*)d_in[4];
    const float* q_w  =(const float*)d_in[5];
    const float* q_b  =(const float*)d_in[6];
    const float* inw  =(const float*)d_in[7];
    const float* inb  =(const float*)d_in[8];
    const float* opw  =(const float*)d_in[9];
    const float* opb  =(const float*)d_in[10];
    const float* Wq   =(const float*)d_in[11];
    const float* Wk   =(const float*)d_in[12];
    const float* Wv   =(const float*)d_in[13];
    const float* synw =(const float*)d_in[14];
    const float* synb =(const float*)d_in[15];
    const float* slns =(const float*)d_in[16];
    const float* slnb =(const float*)d_in[17];
    const float* w1   =(const float*)d_in[18];
    const float* b1   =(const float*)d_in[19];
    const float* w2   =(const float*)d_in[20];
    const float* b2   =(const float*)d_in[21];
    const float* sas  =(const float*)d_in[22];
    const float* strc =(const float*)d_in[23];
    const float* outw =(const float*)d_in[24];
    const float* outb =(const float*)d_in[25];
    float* out=(float*)d_out;

    float *p_kv,*p_KV,*p_W,*p_MqT,*p_beff,*p_synw2,*p_bsyn,*p_Qb,*p_Kb;
    float *p_st,*p_act,*p_sync,*p_pre2,*p_P;
    cudaGetSymbolAddress((void**)&p_kv,   g_kv);
    cudaGetSymbolAddress((void**)&p_KV,   g_KV);
    cudaGetSymbolAddress((void**)&p_W,    g_Wqkv);
    cudaGetSymbolAddress((void**)&p_MqT,  g_MqT);
    cudaGetSymbolAddress((void**)&p_beff, g_beff);
    cudaGetSymbolAddress((void**)&p_synw2,g_synw2);
    cudaGetSymbolAddress((void**)&p_bsyn, g_bsyn);
    cudaGetSymbolAddress((void**)&p_Qb,   g_Qb);
    cudaGetSymbolAddress((void**)&p_Kb,   g_Kb);
    cudaGetSymbolAddress((void**)&p_st,   g_st);
    cudaGetSymbolAddress((void**)&p_act,  g_act);
    cudaGetSymbolAddress((void**)&p_sync, g_sync);
    cudaGetSymbolAddress((void**)&p_pre2, g_pre2);
    cudaGetSymbolAddress((void**)&p_P,    g_P);

    // ---- setup: folded weights + KV cache ----
    k_copyW<<<(3*DM*DM+255)/256,256>>>(Wq,Wk,Wv,p_W);
    k_initact<<<(B_*DM+255)/256,256>>>(sas,p_act,p_pre2);
    k_initst<<<(MEMN*DM*B_+255)/256,256>>>(strc,p_st);
    k_gemm<<<dim3(DI/64,MS/64,1),256>>>(x,kv_w,p_KV,nullptr,MS,DI,DI,DI);
    k_lnkv<<<MS,256>>>(p_KV,kv_b,lnks,lnkb,p_kv);
    k_gemm<<<dim3(DM/64,MS/64,1),256>>>(p_kv,inw+(size_t)DI*DI,p_KV,inb+DI,MS,DM,DI,DI);
    // MqT = (wq_c @ q_w)^T   (store transposed for coalesced cross reads)
    k_gemm_tn<<<dim3(DM/64,DI/64),256>>>(inw,q_w,p_MqT,DI,DM,DI,DI,1);
    // Wsyn' cols 0:512 = syn_w[:, :512] @ opw ; cols 512:1536 = syn_w[:, 512:]
    k_gemm_tn<<<dim3(DI/64,2048/64),256>>>(synw,opw,p_synw2,1536,DI,1536,DI,0);
    k_copyW2<<<(2048*1024+255)/256,256>>>(synw,p_synw2);
    k_bvec<<<2,256>>>(inw,DI,DI,q_b,inb,p_beff,DI);       // wq_c@q_b + bq_c
    k_bvec<<<8,256>>>(synw,1536,DI,opb,synb,p_bsyn,2048); // syn_w[:, :512]@opb + syn_b
    // ---- initial sync (fills rings) ----
    k_gemm<<<dim3(48,1,16),256>>>(p_act,p_W,p_P,nullptr,B_,3*DM,DM,64);
    k_sync<<<dim3(B_,8),128>>>(p_P,p_Qb,p_Kb,p_sync,nullptr,0,1,16);

    // ---- 50 thought ticks ----
    for(int t=0;t<ITERS;t++){
        k_cross<<<dim3(B_,8),256>>>(p_MqT,p_beff,p_sync,p_KV,p_pre2);
        k_gemm<<<dim3(32,1,24),256>>>(p_pre2,p_synw2,p_P,nullptr,B_,2048,1536,64);
        k_synep<<<B_,256>>>(p_P,p_bsyn,slns,slnb,p_st,t%MEMN,24);
        k_nlm<<<DM/4,256>>>(p_st,w1,b1,w2,b2,p_act,p_pre2,t);
        k_gemm<<<dim3(48,1,16),256>>>(p_act,p_W,p_P,nullptr,B_,3*DM,DM,64);
        k_sync<<<dim3(B_,8),128>>>(p_P,p_Qb,p_Kb,p_sync,
                                   (t==ITERS-1)?(out+OFF_SYNC):nullptr,t%MEMN,0,16);
        k_gemm<<<dim3(16,1,16),256>>>(p_sync,outw,p_P,nullptr,B_,OUTN,DM,64);
        k_pred<<<B_,256>>>(p_P,outb,out,t,16);
    }
}

// round 12
// speedup vs baseline: 1.3664x; 1.2042x over previous
#include <cuda_runtime.h>
#include <math.h>

#define B_    64
#define S_    196
#define DM    1024
#define DI    512
#define MEMN  25
#define ITERS 50
#define OUTN  1000
#define MS    (B_*S_)
#define NB    128

#define OFF_CERT (B_*OUTN*ITERS)
#define OFF_SYNC (OFF_CERT + B_*2*ITERS)

// ------------------------- device scratch ----------------------------------
__device__ __align__(16) float g_kv   [MS*DI];
__device__ __align__(16) float g_KV   [MS*DM];
__device__ __align__(16) float g_Wqkv [3*DM*DM];
__device__ __align__(16) float g_Mq   [DI*DM];       // (wq_c@q_w) row-major [512][1024]
__device__ __align__(16) float g_beff [DI];
__device__ __align__(16) float g_synw2[2048*1536];
__device__ __align__(16) float g_bsyn [2048];
__device__ __align__(16) float g_Qb   [B_*MEMN*DM];
__device__ __align__(16) float g_Kb   [B_*MEMN*DM];
__device__ __align__(16) float g_st   [MEMN*DM*B_];
__device__ __align__(16) float g_act  [B_*DM];
__device__ __align__(16) float g_sync [B_*DM];
__device__ __align__(16) float g_pre2 [B_*1536];
__device__ __align__(16) float g_Pq   [8*B_*DI];
__device__ __align__(16) float g_Po   [8*B_*OUTN];
__device__ __align__(16) float g_Ps   [12*B_*2048];
__device__ __align__(16) float g_Pk   [8*B_*3*DM];
__device__ unsigned g_barCnt;

// ------------------------- reductions --------------------------------------
__device__ __forceinline__ float warpSum(float v){
    #pragma unroll
    for(int o=16;o;o>>=1) v += __shfl_down_sync(0xffffffffu,v,o);
    return v;
}
__device__ __forceinline__ float warpMax(float v){
    #pragma unroll
    for(int o=16;o;o>>=1) v = fmaxf(v,__shfl_down_sync(0xffffffffu,v,o));
    return v;
}
__device__ float blockSum(float v, float* buf){
    int lane=threadIdx.x&31, w=threadIdx.x>>5, nw=(blockDim.x+31)>>5;
    v=warpSum(v);
    if(lane==0) buf[w]=v;
    __syncthreads();
    v=(threadIdx.x<nw)?buf[threadIdx.x]:0.f;
    if(w==0) v=warpSum(v);
    if(threadIdx.x==0) buf[0]=v;
    __syncthreads();
    float r=buf[0]; __syncthreads(); return r;
}
__device__ float blockMax(float v, float* buf){
    int lane=threadIdx.x&31, w=threadIdx.x>>5, nw=(blockDim.x+31)>>5;
    v=warpMax(v);
    if(lane==0) buf[w]=v;
    __syncthreads();
    v=(threadIdx.x<nw)?buf[threadIdx.x]:-1e30f;
    if(w==0) v=warpMax(v);
    if(threadIdx.x==0) buf[0]=v;
    __syncthreads();
    float r=buf[0]; __syncthreads(); return r;
}
__device__ __forceinline__ float sigm(float x){ return 1.f/(1.f+__expf(-x)); }

// ------------------------- grid barrier ------------------------------------
__device__ __forceinline__ void gsync(unsigned &target){
    __threadfence();
    __syncthreads();
    target += NB;
    if(threadIdx.x==0){
        atomicAdd(&g_barCnt,1u);
        while(*(volatile unsigned*)&g_barCnt < target) __nanosleep(64);
        __threadfence();
    }
    __syncthreads();
}

// ------------------------- setup: split-K SGEMM (A rm MxK, W rm NxK) -------
__global__ void __launch_bounds__(256) k_gemm(const float* __restrict__ A,
                                              const float* __restrict__ W,
                                              float* __restrict__ P,
                                              const float* __restrict__ bias,
                                              int M,int N,int K,int kchunk){
    __shared__ float As[16][64];
    __shared__ float Ws[16][64];
    const int n0=blockIdx.x*64, m0=blockIdx.y*64, k0=blockIdx.z*kchunk;
    const int tid=threadIdx.x;
    const int tx=tid&15, ty=tid>>4;
    const int lr=tid>>2, lc=tid&3;
    float c[4][4];
    #pragma unroll
    for(int i=0;i<4;i++){c[i][0]=0;c[i][1]=0;c[i][2]=0;c[i][3]=0;}
    const float* Ab = A + (size_t)(m0+lr)*K + k0 + lc*4;
    const bool wok = (n0+lr)<N;
    const float* Wb = W + (size_t)(n0+lr)*K + k0 + lc*4;
    for(int kk=0; kk<kchunk; kk+=16){
        float4 av = *(const float4*)(Ab+kk);
        float4 wv = wok ? *(const float4*)(Wb+kk) : make_float4(0,0,0,0);
        __syncthreads();
        As[lc*4+0][lr]=av.x; As[lc*4+1][lr]=av.y; As[lc*4+2][lr]=av.z; As[lc*4+3][lr]=av.w;
        Ws[lc*4+0][lr]=wv.x; Ws[lc*4+1][lr]=wv.y; Ws[lc*4+2][lr]=wv.z; Ws[lc*4+3][lr]=wv.w;
        __syncthreads();
        #pragma unroll
        for(int q=0;q<16;q++){
            float4 a=*(const float4*)&As[q][ty*4];
            float4 w=*(const float4*)&Ws[q][tx*4];
            c[0][0]+=a.x*w.x; c[0][1]+=a.x*w.y; c[0][2]+=a.x*w.z; c[0][3]+=a.x*w.w;
            c[1][0]+=a.y*w.x; c[1][1]+=a.y*w.y; c[1][2]+=a.y*w.z; c[1][3]+=a.y*w.w;
            c[2][0]+=a.z*w.x; c[2][1]+=a.z*w.y; c[2][2]+=a.z*w.z; c[2][3]+=a.z*w.w;
            c[3][0]+=a.w*w.x; c[3][1]+=a.w*w.y; c[3][2]+=a.w*w.z; c[3][3]+=a.w*w.w;
        }
    }
    float* Pb = P + ((size_t)blockIdx.z*M + m0)*N + n0;
    #pragma unroll
    for(int i=0;i<4;i++){
        int m=ty*4+i;
        #pragma unroll
        for(int j=0;j<4;j++){
            int n=tx*4+j;
            if(n0+n<N){
                float v=c[i][j];
                if(bias) v+=bias[n0+n];
                Pb[(size_t)m*N+n]=v;
            }
        }
    }
}

// ------------------------- setup: TN GEMM C = A(MxK)@B(KxN) ----------------
__global__ void __launch_bounds__(256) k_gemm_tn(const float* __restrict__ A,
                                                 const float* __restrict__ B,
                                                 float* __restrict__ C,
                                                 int lda,int ldb,int ldc,int K,int transC){
    __shared__ float As[16][64];
    __shared__ float Bs[16][64];
    const int n0=blockIdx.x*64, m0=blockIdx.y*64;
    const int tid=threadIdx.x;
    const int tx=tid&15, ty=tid>>4;
    const int lr=tid>>2, lc=tid&3;
    const int br=tid>>4, bc=(tid&15)*4;
    float c[4][4];
    #pragma unroll
    for(int i=0;i<4;i++){c[i][0]=0;c[i][1]=0;c[i][2]=0;c[i][3]=0;}
    for(int k0=0;k0<K;k0+=16){
        float4 av=*(const float4*)(A+(size_t)(m0+lr)*lda + k0 + lc*4);
        float4 bv=*(const float4*)(B+(size_t)(k0+br)*ldb + n0 + bc);
        __syncthreads();
        As[lc*4+0][lr]=av.x; As[lc*4+1][lr]=av.y; As[lc*4+2][lr]=av.z; As[lc*4+3][lr]=av.w;
        *(float4*)&Bs[br][bc]=bv;
        __syncthreads();
        #pragma unroll
        for(int q=0;q<16;q++){
            float4 a=*(const float4*)&As[q][ty*4];
            float4 w=*(const float4*)&Bs[q][tx*4];
            c[0][0]+=a.x*w.x; c[0][1]+=a.x*w.y; c[0][2]+=a.x*w.z; c[0][3]+=a.x*w.w;
            c[1][0]+=a.y*w.x; c[1][1]+=a.y*w.y; c[1][2]+=a.y*w.z; c[1][3]+=a.y*w.w;
            c[2][0]+=a.z*w.x; c[2][1]+=a.z*w.y; c[2][2]+=a.z*w.z; c[2][3]+=a.z*w.w;
            c[3][0]+=a.w*w.x; c[3][1]+=a.w*w.y; c[3][2]+=a.w*w.z; c[3][3]+=a.w*w.w;
        }
    }
    #pragma unroll
    for(int i=0;i<4;i++){
        #pragma unroll
        for(int j=0;j<4;j++){
            int m=m0+ty*4+i, n=n0+tx*4+j;
            if(transC) C[(size_t)n*ldc+m]=c[i][j];
            else       C[(size_t)m*ldc+n]=c[i][j];
        }
    }
}

// ------------------------- setup small kernels ------------------------------
__global__ void k_copyW(const float* __restrict__ wq,const float* __restrict__ wk,
                        const float* __restrict__ wv,float* __restrict__ dst){
    int i=blockIdx.x*blockDim.x+threadIdx.x;
    if(i>=3*DM*DM) return;
    int part=i/(DM*DM), r=i%(DM*DM);
    dst[i]=(part==0)?wq[r]:(part==1)?wk[r]:wv[r];
}
__global__ void k_copyW2(const float* __restrict__ synw,float* __restrict__ dst){
    int i=blockIdx.x*blockDim.x+threadIdx.x;
    if(i>=2048*1024) return;
    int m=i>>10, k=i&1023;
    dst[(size_t)m*1536+512+k]=synw[(size_t)m*1536+512+k];
}
__global__ void k_initact(const float* __restrict__ sas,float* __restrict__ act,
                          float* __restrict__ pre2){
    int i=blockIdx.x*blockDim.x+threadIdx.x;
    if(i>=B_*DM) return;
    float v=sas[i&(DM-1)];
    act[i]=v;
    pre2[(size_t)(i>>10)*1536 + 512 + (i&(DM-1))]=v;
}
__global__ void k_initst(const float* __restrict__ strace,float* __restrict__ st){
    int i=blockIdx.x*blockDim.x+threadIdx.x;
    if(i>=MEMN*DM*B_) return;
    int slot=i/(DM*B_), r=i%(DM*B_), d=r/B_;
    st[i]=strace[d*MEMN+slot];
}
__global__ void k_lnkv(const float* __restrict__ tmp,const float* __restrict__ kvb,
                       const float* __restrict__ lns,const float* __restrict__ lnb,
                       float* __restrict__ kv){
    __shared__ float red[33];
    int r=blockIdx.x, tid=threadIdx.x;
    float v0=tmp[r*DI+tid]+kvb[tid];
    float v1=tmp[r*DI+tid+256]+kvb[tid+256];
    float s=blockSum(v0+v1,red);
    float sq=blockSum(v0*v0+v1*v1,red);
    float mean=s*(1.f/DI);
    float var=sq*(1.f/DI)-mean*mean;
    float rstd=rsqrtf(var+1e-5f);
    kv[r*DI+tid]    =(v0-mean)*rstd*lns[tid]    +lnb[tid];
    kv[r*DI+tid+256]=(v1-mean)*rstd*lns[tid+256]+lnb[tid+256];
}
__global__ void k_bvec(const float* __restrict__ W,int lda,int K,
                       const float* __restrict__ v,const float* __restrict__ b0,
                       float* __restrict__ o,int n){
    int i=blockIdx.x*blockDim.x+threadIdx.x;
    if(i>=n) return;
    float a=b0[i];
    const float* wr=W+(size_t)i*lda;
    for(int k=0;k<K;k++) a+=wr[k]*v[k];
    o[i]=a;
}
__global__ void k_zero(unsigned* p){ if(threadIdx.x==0) *p=0; }

// ======================= megakernel phase workers ===========================
// in-kernel split-K gemm unit: M=64 fixed, A row stride = W row stride = Ksrc
__device__ void unit_gemm(const float* __restrict__ A,const float* __restrict__ W,
                          float* __restrict__ P,int N,int Ksrc,
                          int n0,int z,float* sm){
    float (*As)[64]=(float(*)[64])sm;
    float (*Ws)[64]=(float(*)[64])(sm+1024);
    const int tid=threadIdx.x;
    const int tx=tid&15, ty=tid>>4;
    const int lr=tid>>2, lc=tid&3;
    const int k0=z*128;
    float c[4][4];
    #pragma unroll
    for(int i=0;i<4;i++){c[i][0]=0;c[i][1]=0;c[i][2]=0;c[i][3]=0;}
    const float* Ab=A+(size_t)lr*Ksrc + k0 + lc*4;
    const bool wok=(n0+lr)<N;
    const float* Wb=W+(size_t)(n0+lr)*Ksrc + k0 + lc*4;
    for(int kk=0;kk<128;kk+=16){
        float4 av=*(const float4*)(Ab+kk);
        float4 wv=wok?*(const float4*)(Wb+kk):make_float4(0,0,0,0);
        __syncthreads();
        As[lc*4+0][lr]=av.x; As[lc*4+1][lr]=av.y; As[lc*4+2][lr]=av.z; As[lc*4+3][lr]=av.w;
        Ws[lc*4+0][lr]=wv.x; Ws[lc*4+1][lr]=wv.y; Ws[lc*4+2][lr]=wv.z; Ws[lc*4+3][lr]=wv.w;
        __syncthreads();
        #pragma unroll
        for(int q=0;q<16;q++){
            float4 a=*(const float4*)&As[q][ty*4];
            float4 w=*(const float4*)&Ws[q][tx*4];
            c[0][0]+=a.x*w.x; c[0][1]+=a.x*w.y; c[0][2]+=a.x*w.z; c[0][3]+=a.x*w.w;
            c[1][0]+=a.y*w.x; c[1][1]+=a.y*w.y; c[1][2]+=a.y*w.z; c[1][3]+=a.y*w.w;
            c[2][0]+=a.z*w.x; c[2][1]+=a.z*w.y; c[2][2]+=a.z*w.z; c[2][3]+=a.z*w.w;
            c[3][0]+=a.w*w.x; c[3][1]+=a.w*w.y; c[3][2]+=a.w*w.z; c[3][3]+=a.w*w.w;
        }
    }
    __syncthreads();
    float* Pb=P+((size_t)z*64)*N + n0;
    #pragma unroll
    for(int i=0;i<4;i++){
        int m=ty*4+i;
        #pragma unroll
        for(int j=0;j<4;j++){
            int n=tx*4+j;
            if(n0+n<N) Pb[(size_t)m*N+n]=c[i][j];
        }
    }
}

__device__ void unit_crossatt(int b,int h,const float* __restrict__ beff,
                              float* __restrict__ pre2,float* sm){
    float* q2s=sm;          // 64
    float* ws =sm+64;       // 196
    float* os =sm+260;      // 256
    float* red=sm+520;      // 33
    const int tid=threadIdx.x;
    __syncthreads();
    if(tid<64){
        float a=beff[h*64+tid];
        #pragma unroll
        for(int z=0;z<8;z++) a+=g_Pq[((size_t)z*64+b)*DI + h*64+tid];
        q2s[tid]=a;
    }
    __syncthreads();
    float sv=-1e30f;
    if(tid<S_){
        const float* kr=g_KV+((size_t)(b*S_+tid))*DM + h*64;
        float a=0.f;
        #pragma unroll 8
        for(int dd=0;dd<64;dd++) a+=q2s[dd]*kr[dd];
        sv=a*0.125f;
    }
    float mxv=blockMax(sv,red);
    float ev=(tid<S_)?__expf(sv-mxv):0.f;
    float Z=blockSum(ev,red);
    if(tid<S_) ws[tid]=ev/Z;
    __syncthreads();
    int dd=tid&63, part=tid>>6;
    float acc=0.f;
    for(int s=part*49;s<part*49+49;s++)
        acc+=ws[s]*g_KV[((size_t)(b*S_+s))*DM + DI + h*64 + dd];
    os[part*64+dd]=acc;
    __syncthreads();
    if(tid<64)
        pre2[(size_t)b*1536 + h*64 + tid]=os[tid]+os[64+tid]+os[128+tid]+os[192+tid];
}

__device__ void unit_pred(int b,const float* __restrict__ ob,
                          float* __restrict__ out,int t,float* sm){
    float* pv=sm;           // 1000
    float* red=sm+1000;     // 33
    const int tid=threadIdx.x;
    __syncthreads();
    float lmax=-1e30f;
    for(int j=tid;j<OUTN;j+=256){
        float v=ob[j];
        const float* p=g_Po+(size_t)b*OUTN + j;
        #pragma unroll
        for(int z=0;z<8;z++){ v+=p[0]; p+=(size_t)64*OUTN; }
        pv[j]=v;
        out[((size_t)b*OUTN+j)*ITERS+t]=v;
        lmax=fmaxf(lmax,v);
    }
    float mx=blockMax(lmax,red);
    float lz=0.f, ls1=0.f;
    for(int j=tid;j<OUTN;j+=256){
        float e=__expf(pv[j]-mx);
        lz+=e; ls1+=e*pv[j];
    }
    float Z=blockSum(lz,red);
    float S1=blockSum(ls1,red);
    if(tid==0){
        float logZ=logf(Z);
        float plogp=S1/Z - mx - logZ;
        float ne=-plogp*(1.f/logf((float)OUTN));
        out[OFF_CERT + ((size_t)b*2+0)*ITERS + t]=ne;
        out[OFF_CERT + ((size_t)b*2+1)*ITERS + t]=1.f-ne;
    }
}

__device__ void unit_synep(int b,const float* __restrict__ lns,
                           const float* __restrict__ lnb,int w,float* sm){
    float* vals=sm;         // 1024
    float* red=sm+1024;     // 33
    const int tid=threadIdx.x;
    __syncthreads();
    float s=0.f, sq=0.f;
    #pragma unroll
    for(int r=0;r<4;r++){
        int j=tid+r*256;
        float a=g_bsyn[j], g=g_bsyn[DM+j];
        const float* p=g_Ps+(size_t)b*2048 + j;
        #pragma unroll
        for(int z=0;z<12;z++){
            a+=p[0]; g+=p[DM];
            p+=(size_t)64*2048;
        }
        float v=a*sigm(g);
        vals[j]=v; s+=v; sq+=v*v;
    }
    s=blockSum(s,red); sq=blockSum(sq,red);
    float mean=s*(1.f/DM);
    float var=sq*(1.f/DM)-mean*mean;
    float rstd=rsqrtf(var+1e-5f);
    #pragma unroll
    for(int r=0;r<4;r++){
        int j=tid+r*256;
        g_st[((size_t)w*DM + j)*B_ + b]=(vals[j]-mean)*rstd*lns[j]+lnb[j];
    }
}

__device__ void unit_nlm(int u,const float* __restrict__ w1,const float* __restrict__ b1,
                         const float* __restrict__ w2,const float* __restrict__ b2,
                         int t,float* sm){
    float* w1s=sm;          // 3200
    float* b1s=sm+3200;     // 128
    float* w2s=sm+3328;     // 128
    float* b2s=sm+3456;     // 8
    const int tid=threadIdx.x, d0=u*4;
    __syncthreads();
    for(int i=tid;i<MEMN*32*4;i+=256){
        int m=i>>7, r=i&127, j=r>>2, dl=r&3;
        w1s[i]=w1[(size_t)(m*32+j)*DM + d0+dl];
    }
    if(tid<128){ int j=tid>>2, dl=tid&3; b1s[tid]=b1[(d0+dl)*32+j]; }
    else {
        int i=tid-128; int hh=i>>3, o=(i>>2)&1, dl=i&3;
        w2s[i]=w2[(size_t)(hh*2+o)*DM + d0+dl];
    }
    if(tid<8){ int o=tid>>2, dl=tid&3; b2s[tid]=b2[(d0+dl)*2+o]; }
    __syncthreads();
    int b=tid&63, dl=tid>>6, d=d0+dl;
    float stv[MEMN];
    #pragma unroll
    for(int m=0;m<MEMN;m++){
        int phys=(t+1+m)%MEMN;
        stv[m]=g_st[((size_t)phys*DM + d)*B_ + b];
    }
    float o0=0.f,o1=0.f;
    #pragma unroll
    for(int j=0;j<16;j++){
        float a=b1s[j*4+dl], g=b1s[(j+16)*4+dl];
        #pragma unroll
        for(int m=0;m<MEMN;m++){
            a+=stv[m]*w1s[(m*32+j)*4+dl];
            g+=stv[m]*w1s[(m*32+j+16)*4+dl];
        }
        float hv=a*sigm(g);
        o0+=hv*w2s[(j*2+0)*4+dl];
        o1+=hv*w2s[(j*2+1)*4+dl];
    }
    o0+=b2s[0*4+dl]; o1+=b2s[1*4+dl];
    float v=o0*sigm(o1);
    g_act[b*DM+d]=v;
    g_pre2[(size_t)b*1536 + 512 + d]=v;
}

__device__ void unit_sync(int b,int h,int slot,int fillAll,
                          float* __restrict__ outOpt,float* sm){
    float* Ks=sm;           // 25*128
    float* Vs=sm+3200;      // 128
    const int tid=threadIdx.x;
    __syncthreads();
    float q[MEMN];
    if(tid<128){
        int d=tid, col=h*128+d;
        float nq=0.f,nk=0.f,nv=0.f;
        const float* row=g_Pk+(size_t)b*3072 + col;
        #pragma unroll
        for(int z=0;z<8;z++){
            nq+=row[0]; nk+=row[1024]; nv+=row[2048];
            row+=(size_t)64*3072;
        }
        if(fillAll){
            #pragma unroll
            for(int m=0;m<MEMN;m++){
                g_Qb[(b*MEMN+m)*DM+col]=nq;
                g_Kb[(b*MEMN+m)*DM+col]=nk;
                q[m]=nq; Ks[m*128+d]=nk;
            }
        }else{
            g_Qb[(b*MEMN+slot)*DM+col]=nq;
            g_Kb[(b*MEMN+slot)*DM+col]=nk;
            #pragma unroll
            for(int m=0;m<MEMN;m++){
                q[m]       =(m==slot)?nq:g_Qb[(b*MEMN+m)*DM+col];
                Ks[m*128+d]=(m==slot)?nk:g_Kb[(b*MEMN+m)*DM+col];
            }
        }
        Vs[d]=nv;
    }
    __syncthreads();
    if(tid<128){
        int d=tid;
        const float sc=0.08838834764831845f;   // 1/sqrt(128)
        float mx=-1e30f, Z=0.f, acc=0.f;
        for(int e=0;e<128;e+=4){
            float s0=0,s1=0,s2=0,s3=0;
            #pragma unroll
            for(int m=0;m<MEMN;m++){
                float qm=q[m];
                s0+=qm*Ks[m*128+e];   s1+=qm*Ks[m*128+e+1];
                s2+=qm*Ks[m*128+e+2]; s3+=qm*Ks[m*128+e+3];
            }
            s0*=sc; s1*=sc; s2*=sc; s3*=sc;
            float m2=fmaxf(mx,fmaxf(fmaxf(s0,s1),fmaxf(s2,s3)));
            float cc=__expf(mx-m2);
            float e0=__expf(s0-m2),e1=__expf(s1-m2),e2=__expf(s2-m2),e3=__expf(s3-m2);
            Z  = Z*cc + e0+e1+e2+e3;
            acc= acc*cc + e0*Vs[e]+e1*Vs[e+1]+e2*Vs[e+2]+e3*Vs[e+3];
            mx=m2;
        }
        float att=acc/Z;
        g_sync[b*DM + d*8 + h]=att;
        if(outOpt) outOpt[b*DM + d*8 + h]=att;
    }
    __syncthreads();
}

// ======================= the megakernel =====================================
__global__ void __launch_bounds__(256) k_mega(
    const float* __restrict__ beff,
    const float* __restrict__ slns, const float* __restrict__ slnb,
    const float* __restrict__ w1, const float* __restrict__ b1,
    const float* __restrict__ w2, const float* __restrict__ b2,
    const float* __restrict__ outw, const float* __restrict__ outb,
    float* __restrict__ out)
{
    __shared__ float sm[3600];
    unsigned target=0;

    // pre-loop: project initial activation, fill rings, compute sync_a(0)
    for(int u=blockIdx.x; u<384; u+=NB)
        unit_gemm(g_act, g_Wqkv, g_Pk, 3*DM, DM, (u%48)*64, u/48, sm);
    gsync(target);
    for(int u=blockIdx.x; u<512; u+=NB)
        unit_sync(u>>3, u&7, 0, 1, nullptr, sm);
    gsync(target);

    for(int t=0;t<ITERS;t++){
        // P1: cross-Q GEMM (64) + output-head GEMM for tick t-1 (128)
        int nU1 = (t==0)?64:192;
        for(int u=blockIdx.x; u<nU1; u+=NB){
            if(u<64) unit_gemm(g_sync, g_Mq, g_Pq, DI, DM, (u&7)*64, u>>3, sm);
            else { int v=u-64; unit_gemm(g_sync, outw, g_Po, OUTN, DM, (v&15)*64, v>>4, sm); }
        }
        gsync(target);
        // P2: cross attention (512) + pred for tick t-1 (64)
        int nU2 = (t==0)?512:576;
        for(int u=blockIdx.x; u<nU2; u+=NB){
            if(u<512) unit_crossatt(u>>3, u&7, beff, g_pre2, sm);
            else unit_pred(u-512, outb, out, t-1, sm);
        }
        gsync(target);
        // P3: synapse GEMM 64x2048x1536, 32 ntiles x 12 kparts
        for(int u=blockIdx.x; u<384; u+=NB)
            unit_gemm(g_pre2, g_synw2, g_Ps, 2048, 1536, (u&31)*64, u>>5, sm);
        gsync(target);
        // P4: GLU+LN -> trace slot
        for(int u=blockIdx.x; u<64; u+=NB)
            unit_synep(u, slns, slnb, t%MEMN, sm);
        gsync(target);
        // P5: per-neuron NLM
        for(int u=blockIdx.x; u<256; u+=NB)
            unit_nlm(u, w1, b1, w2, b2, t, sm);
        gsync(target);
        // P6: QKV projection of new activation
        for(int u=blockIdx.x; u<384; u+=NB)
            unit_gemm(g_act, g_Wqkv, g_Pk, 3*DM, DM, (u%48)*64, u/48, sm);
        gsync(target);
        // P7: sync attention + ring update
        for(int u=blockIdx.x; u<512; u+=NB)
            unit_sync(u>>3, u&7, t%MEMN, 0,
                      (t==ITERS-1)?(out+OFF_SYNC):nullptr, sm);
        gsync(target);
    }
    // tail: output head + pred for tick 49
    for(int u=blockIdx.x; u<128; u+=NB)
        unit_gemm(g_sync, outw, g_Po, OUTN, DM, (u&15)*64, u>>4, sm);
    gsync(target);
    for(int u=blockIdx.x; u<64; u+=NB)
        unit_pred(u, outb, out, ITERS-1, sm);
}

// ------------------------- host driver -------------------------------------
extern "C" void kernel_launch(void* const* d_in, const int* in_sizes, int n_in,
                              void* d_out, int out_size){
    (void)in_sizes; (void)n_in; (void)out_size;
    const float* x    =(const float*)d_in[0];
    const float* kv_w =(const float*)d_in[1];
    const float* kv_b =(const float*)d_in[2];
    const float* lnks =(const float*)d_in[3];
    const float* lnkb =(const float*)d_in[4];
    const float* q_w  =(const float*)d_in[5];
    const float* q_b  =(const float*)d_in[6];
    const float* inw  =(const float*)d_in[7];
    const float* inb  =(const float*)d_in[8];
    const float* opw  =(const float*)d_in[9];
    const float* opb  =(const float*)d_in[10];
    const float* Wq   =(const float*)d_in[11];
    const float* Wk   =(const float*)d_in[12];
    const float* Wv   =(const float*)d_in[13];
    const float* synw =(const float*)d_in[14];
    const float* synb =(const float*)d_in[15];
    const float* slns =(const float*)d_in[16];
    const float* slnb =(const float*)d_in[17];
    const float* w1   =(const float*)d_in[18];
    const float* b1   =(const float*)d_in[19];
    const float* w2   =(const float*)d_in[20];
    const float* b2   =(const float*)d_in[21];
    const float* sas  =(const float*)d_in[22];
    const float* strc =(const float*)d_in[23];
    const float* outw =(const float*)d_in[24];
    const float* outb =(const float*)d_in[25];
    float* out=(float*)d_out;

    float *p_kv,*p_KV,*p_W,*p_Mq,*p_beff,*p_synw2,*p_bsyn,*p_act,*p_pre2,*p_st;
    unsigned* p_bar;
    cudaGetSymbolAddress((void**)&p_kv,   g_kv);
    cudaGetSymbolAddress((void**)&p_KV,   g_KV);
    cudaGetSymbolAddress((void**)&p_W,    g_Wqkv);
    cudaGetSymbolAddress((void**)&p_Mq,   g_Mq);
    cudaGetSymbolAddress((void**)&p_beff, g_beff);
    cudaGetSymbolAddress((void**)&p_synw2,g_synw2);
    cudaGetSymbolAddress((void**)&p_bsyn, g_bsyn);
    cudaGetSymbolAddress((void**)&p_act,  g_act);
    cudaGetSymbolAddress((void**)&p_pre2, g_pre2);
    cudaGetSymbolAddress((void**)&p_st,   g_st);
    cudaGetSymbolAddress((void**)&p_bar,  g_barCnt);

    // ---- setup: folded weights + KV cache ----
    k_copyW<<<(3*DM*DM+255)/256,256>>>(Wq,Wk,Wv,p_W);
    k_initact<<<(B_*DM+255)/256,256>>>(sas,p_act,p_pre2);
    k_initst<<<(MEMN*DM*B_+255)/256,256>>>(strc,p_st);
    k_gemm<<<dim3(DI/64,MS/64,1),256>>>(x,kv_w,p_KV,nullptr,MS,DI,DI,DI);
    k_lnkv<<<MS,256>>>(p_KV,kv_b,lnks,lnkb,p_kv);
    k_gemm<<<dim3(DM/64,MS/64,1),256>>>(p_kv,inw+(size_t)DI*DI,p_KV,inb+DI,MS,DM,DI,DI);
    // Mq = wq_c @ q_w  (512 x 1024, row-major)
    k_gemm_tn<<<dim3(DM/64,DI/64),256>>>(inw,q_w,p_Mq,DI,DM,DM,DI,0);
    // folded synapse weight: cols 0:512 = syn_w[:,:512]@opw ; cols 512:1536 copied
    k_gemm_tn<<<dim3(DI/64,2048/64),256>>>(synw,opw,p_synw2,1536,DI,1536,DI,0);
    k_copyW2<<<(2048*1024+255)/256,256>>>(synw,p_synw2);
    k_bvec<<<2,256>>>(inw,DI,DI,q_b,inb,p_beff,DI);
    k_bvec<<<8,256>>>(synw,1536,DI,opb,synb,p_bsyn,2048);
    // ---- megakernel: all 50 ticks ----
    k_zero<<<1,32>>>(p_bar);
    k_mega<<<NB,256>>>(p_beff,slns,slnb,w1,b1,w2,b2,outw,outb,out);
}

// round 13
// speedup vs baseline: 1.5610x; 1.1424x over previous
#include <cuda_runtime.h>
#include <math.h>

#define B_    64
#define S_    196
#define DM    1024
#define DI    512
#define MEMN  25
#define ITERS 50
#define OUTN  1000
#define MS    (B_*S_)
#define NB    256

#define OFF_CERT (B_*OUTN*ITERS)
#define OFF_SYNC (OFF_CERT + B_*2*ITERS)

// ------------------------- device scratch ----------------------------------
__device__ __align__(16) float g_kv   [MS*DI];
__device__ __align__(16) float g_KV   [MS*DM];
__device__ __align__(16) float g_Wqkv [3*DM*DM];
__device__ __align__(16) float g_Mq   [DI*DM];
__device__ __align__(16) float g_beff [DI];
__device__ __align__(16) float g_synw2[2048*1536];
__device__ __align__(16) float g_bsyn [2048];
__device__ __align__(16) float g_Qb   [B_*MEMN*DM];
__device__ __align__(16) float g_Kb   [B_*MEMN*DM];
__device__ __align__(16) float g_st   [MEMN*DM*B_];
__device__ __align__(16) float g_act  [B_*DM];
__device__ __align__(16) float g_sync [B_*DM];
__device__ __align__(16) float g_pre2 [B_*1536];
__device__ __align__(16) float g_S    [B_*8*128*128];   // cached sync scores
__device__ __align__(16) float g_Pq   [16*B_*DI];
__device__ __align__(16) float g_Po   [16*B_*OUTN];
__device__ __align__(16) float g_Ps   [16*B_*2048];
__device__ __align__(16) float g_Pk   [16*B_*3*DM];
__device__ unsigned g_barCnt;

// ------------------------- fast exp (FMA pipe, not MUFU) -------------------
__device__ __forceinline__ float fexp(float x){
    x = fminf(fmaxf(x,-80.f),80.f);
    float y = x*1.442695041f;
    float n = rintf(y);
    float f = y - n;
    float p = 1.3333558e-3f;
    p = fmaf(p,f,9.6181250e-3f);
    p = fmaf(p,f,5.5504110e-2f);
    p = fmaf(p,f,2.4022650e-1f);
    p = fmaf(p,f,6.9314718e-1f);
    p = fmaf(p,f,1.0f);
    return __int_as_float(__float_as_int(p) + (((int)n)<<23));
}
__device__ __forceinline__ float sigm(float x){ return 1.f/(1.f+fexp(-x)); }

// ------------------------- reductions --------------------------------------
__device__ __forceinline__ float warpSum(float v){
    #pragma unroll
    for(int o=16;o;o>>=1) v += __shfl_down_sync(0xffffffffu,v,o);
    return v;
}
__device__ __forceinline__ float warpMax(float v){
    #pragma unroll
    for(int o=16;o;o>>=1) v = fmaxf(v,__shfl_down_sync(0xffffffffu,v,o));
    return v;
}
__device__ float blockSum(float v, float* buf){
    int lane=threadIdx.x&31, w=threadIdx.x>>5, nw=(blockDim.x+31)>>5;
    v=warpSum(v);
    if(lane==0) buf[w]=v;
    __syncthreads();
    v=(threadIdx.x<nw)?buf[threadIdx.x]:0.f;
    if(w==0) v=warpSum(v);
    if(threadIdx.x==0) buf[0]=v;
    __syncthreads();
    float r=buf[0]; __syncthreads(); return r;
}
__device__ float blockMax(float v, float* buf){
    int lane=threadIdx.x&31, w=threadIdx.x>>5, nw=(blockDim.x+31)>>5;
    v=warpMax(v);
    if(lane==0) buf[w]=v;
    __syncthreads();
    v=(threadIdx.x<nw)?buf[threadIdx.x]:-1e30f;
    if(w==0) v=warpMax(v);
    if(threadIdx.x==0) buf[0]=v;
    __syncthreads();
    float r=buf[0]; __syncthreads(); return r;
}

// ------------------------- grid barrier ------------------------------------
__device__ __forceinline__ void gsync(unsigned &target){
    __threadfence();
    __syncthreads();
    target += NB;
    if(threadIdx.x==0){
        atomicAdd(&g_barCnt,1u);
        while(*(volatile unsigned*)&g_barCnt < target) __nanosleep(64);
        __threadfence();
    }
    __syncthreads();
}

// ------------------------- setup: split-K SGEMM ----------------------------
__global__ void __launch_bounds__(256) k_gemm(const float* __restrict__ A,
                                              const float* __restrict__ W,
                                              float* __restrict__ P,
                                              const float* __restrict__ bias,
                                              int M,int N,int K,int kchunk){
    __shared__ float As[16][64];
    __shared__ float Ws[16][64];
    const int n0=blockIdx.x*64, m0=blockIdx.y*64, k0=blockIdx.z*kchunk;
    const int tid=threadIdx.x;
    const int tx=tid&15, ty=tid>>4;
    const int lr=tid>>2, lc=tid&3;
    float c[4][4];
    #pragma unroll
    for(int i=0;i<4;i++){c[i][0]=0;c[i][1]=0;c[i][2]=0;c[i][3]=0;}
    const float* Ab = A + (size_t)(m0+lr)*K + k0 + lc*4;
    const bool wok = (n0+lr)<N;
    const float* Wb = W + (size_t)(n0+lr)*K + k0 + lc*4;
    for(int kk=0; kk<kchunk; kk+=16){
        float4 av = *(const float4*)(Ab+kk);
        float4 wv = wok ? *(const float4*)(Wb+kk) : make_float4(0,0,0,0);
        __syncthreads();
        As[lc*4+0][lr]=av.x; As[lc*4+1][lr]=av.y; As[lc*4+2][lr]=av.z; As[lc*4+3][lr]=av.w;
        Ws[lc*4+0][lr]=wv.x; Ws[lc*4+1][lr]=wv.y; Ws[lc*4+2][lr]=wv.z; Ws[lc*4+3][lr]=wv.w;
        __syncthreads();
        #pragma unroll
        for(int q=0;q<16;q++){
            float4 a=*(const float4*)&As[q][ty*4];
            float4 w=*(const float4*)&Ws[q][tx*4];
            c[0][0]+=a.x*w.x; c[0][1]+=a.x*w.y; c[0][2]+=a.x*w.z; c[0][3]+=a.x*w.w;
            c[1][0]+=a.y*w.x; c[1][1]+=a.y*w.y; c[1][2]+=a.y*w.z; c[1][3]+=a.y*w.w;
            c[2][0]+=a.z*w.x; c[2][1]+=a.z*w.y; c[2][2]+=a.z*w.z; c[2][3]+=a.z*w.w;
            c[3][0]+=a.w*w.x; c[3][1]+=a.w*w.y; c[3][2]+=a.w*w.z; c[3][3]+=a.w*w.w;
        }
    }
    float* Pb = P + ((size_t)blockIdx.z*M + m0)*N + n0;
    #pragma unroll
    for(int i=0;i<4;i++){
        int m=ty*4+i;
        #pragma unroll
        for(int j=0;j<4;j++){
            int n=tx*4+j;
            if(n0+n<N){
                float v=c[i][j];
                if(bias) v+=bias[n0+n];
                Pb[(size_t)m*N+n]=v;
            }
        }
    }
}

// ------------------------- setup: TN GEMM C = A(MxK)@B(KxN) ----------------
__global__ void __launch_bounds__(256) k_gemm_tn(const float* __restrict__ A,
                                                 const float* __restrict__ B,
                                                 float* __restrict__ C,
                                                 int lda,int ldb,int ldc,int K,int transC){
    __shared__ float As[16][64];
    __shared__ float Bs[16][64];
    const int n0=blockIdx.x*64, m0=blockIdx.y*64;
    const int tid=threadIdx.x;
    const int tx=tid&15, ty=tid>>4;
    const int lr=tid>>2, lc=tid&3;
    const int br=tid>>4, bc=(tid&15)*4;
    float c[4][4];
    #pragma unroll
    for(int i=0;i<4;i++){c[i][0]=0;c[i][1]=0;c[i][2]=0;c[i][3]=0;}
    for(int k0=0;k0<K;k0+=16){
        float4 av=*(const float4*)(A+(size_t)(m0+lr)*lda + k0 + lc*4);
        float4 bv=*(const float4*)(B+(size_t)(k0+br)*ldb + n0 + bc);
        __syncthreads();
        As[lc*4+0][lr]=av.x; As[lc*4+1][lr]=av.y; As[lc*4+2][lr]=av.z; As[lc*4+3][lr]=av.w;
        *(float4*)&Bs[br][bc]=bv;
        __syncthreads();
        #pragma unroll
        for(int q=0;q<16;q++){
            float4 a=*(const float4*)&As[q][ty*4];
            float4 w=*(const float4*)&Bs[q][tx*4];
            c[0][0]+=a.x*w.x; c[0][1]+=a.x*w.y; c[0][2]+=a.x*w.z; c[0][3]+=a.x*w.w;
            c[1][0]+=a.y*w.x; c[1][1]+=a.y*w.y; c[1][2]+=a.y*w.z; c[1][3]+=a.y*w.w;
            c[2][0]+=a.z*w.x; c[2][1]+=a.z*w.y; c[2][2]+=a.z*w.z; c[2][3]+=a.z*w.w;
            c[3][0]+=a.w*w.x; c[3][1]+=a.w*w.y; c[3][2]+=a.w*w.z; c[3][3]+=a.w*w.w;
        }
    }
    #pragma unroll
    for(int i=0;i<4;i++){
        #pragma unroll
        for(int j=0;j<4;j++){
            int m=m0+ty*4+i, n=n0+tx*4+j;
            if(transC) C[(size_t)n*ldc+m]=c[i][j];
            else       C[(size_t)m*ldc+n]=c[i][j];
        }
    }
}

// ------------------------- setup small kernels ------------------------------
__global__ void k_copyW(const float* __restrict__ wq,const float* __restrict__ wk,
                        const float* __restrict__ wv,float* __restrict__ dst){
    int i=blockIdx.x*blockDim.x+threadIdx.x;
    if(i>=3*DM*DM) return;
    int part=i/(DM*DM), r=i%(DM*DM);
    dst[i]=(part==0)?wq[r]:(part==1)?wk[r]:wv[r];
}
__global__ void k_copyW2(const float* __restrict__ synw,float* __restrict__ dst){
    int i=blockIdx.x*blockDim.x+threadIdx.x;
    if(i>=2048*1024) return;
    int m=i>>10, k=i&1023;
    dst[(size_t)m*1536+512+k]=synw[(size_t)m*1536+512+k];
}
__global__ void k_initact(const float* __restrict__ sas,float* __restrict__ act,
                          float* __restrict__ pre2){
    int i=blockIdx.x*blockDim.x+threadIdx.x;
    if(i>=B_*DM) return;
    float v=sas[i&(DM-1)];
    act[i]=v;
    pre2[(size_t)(i>>10)*1536 + 512 + (i&(DM-1))]=v;
}
__global__ void k_initst(const float* __restrict__ strace,float* __restrict__ st){
    int i=blockIdx.x*blockDim.x+threadIdx.x;
    if(i>=MEMN*DM*B_) return;
    int slot=i/(DM*B_), r=i%(DM*B_), d=r/B_;
    st[i]=strace[d*MEMN+slot];
}
__global__ void k_lnkv(const float* __restrict__ tmp,const float* __restrict__ kvb,
                       const float* __restrict__ lns,const float* __restrict__ lnb,
                       float* __restrict__ kv){
    __shared__ float red[33];
    int r=blockIdx.x, tid=threadIdx.x;
    float v0=tmp[r*DI+tid]+kvb[tid];
    float v1=tmp[r*DI+tid+256]+kvb[tid+256];
    float s=blockSum(v0+v1,red);
    float sq=blockSum(v0*v0+v1*v1,red);
    float mean=s*(1.f/DI);
    float var=sq*(1.f/DI)-mean*mean;
    float rstd=rsqrtf(var+1e-5f);
    kv[r*DI+tid]    =(v0-mean)*rstd*lns[tid]    +lnb[tid];
    kv[r*DI+tid+256]=(v1-mean)*rstd*lns[tid+256]+lnb[tid+256];
}
__global__ void k_bvec(const float* __restrict__ W,int lda,int K,
                       const float* __restrict__ v,const float* __restrict__ b0,
                       float* __restrict__ o,int n){
    int i=blockIdx.x*blockDim.x+threadIdx.x;
    if(i>=n) return;
    float a=b0[i];
    const float* wr=W+(size_t)i*lda;
    for(int k=0;k<K;k++) a+=wr[k]*v[k];
    o[i]=a;
}
__global__ void k_zero(unsigned* p){ if(threadIdx.x==0) *p=0; }

// ======================= megakernel phase workers ===========================
// 64x128 tile, double-buffered, 4x8 micro. K slab = ksteps*16 at slab z.
__device__ void unit_gemm2(const float* __restrict__ A,const float* __restrict__ W,
                           float* __restrict__ P,int N,int Ksrc,
                           int n0,int z,int ksteps,float* sm){
    float* As=sm;          // [2][16][64]
    float* Bs=sm+2048;     // [2][16][128]
    const int tid=threadIdx.x;
    const int tx=tid&15, ty=tid>>4;
    const int ar=tid>>2, ac=(tid&3)*4;
    const int br=tid>>1, bc=(tid&1)*8;
    const int k0=z*ksteps*16;
    const bool wok=(n0+br)<N;
    const float* Ap=A+(size_t)ar*Ksrc + k0 + ac;
    const float* Wp=W+(size_t)(n0+br)*Ksrc + k0 + bc;
    float c[4][8];
    #pragma unroll
    for(int i=0;i<4;i++)
        #pragma unroll
        for(int j=0;j<8;j++) c[i][j]=0.f;
    float4 a=*(const float4*)Ap;
    float4 b0=wok?*(const float4*)Wp:make_float4(0,0,0,0);
    float4 b1=wok?*(const float4*)(Wp+4):make_float4(0,0,0,0);
    __syncthreads();                       // drain previous unit's smem reads
    for(int s=0;s<ksteps;s++){
        int buf=s&1;
        float* Ab=As+buf*1024;
        float* Bb=Bs+buf*2048;
        Ab[(ac+0)*64+ar]=a.x; Ab[(ac+1)*64+ar]=a.y;
        Ab[(ac+2)*64+ar]=a.z; Ab[(ac+3)*64+ar]=a.w;
        Bb[(bc+0)*128+br]=b0.x; Bb[(bc+1)*128+br]=b0.y;
        Bb[(bc+2)*128+br]=b0.z; Bb[(bc+3)*128+br]=b0.w;
        Bb[(bc+4)*128+br]=b1.x; Bb[(bc+5)*128+br]=b1.y;
        Bb[(bc+6)*128+br]=b1.z; Bb[(bc+7)*128+br]=b1.w;
        __syncthreads();
        if(s+1<ksteps){
            a=*(const float4*)(Ap+(s+1)*16);
            b0=wok?*(const float4*)(Wp+(s+1)*16):make_float4(0,0,0,0);
            b1=wok?*(const float4*)(Wp+(s+1)*16+4):make_float4(0,0,0,0);
        }
        #pragma unroll
        for(int q=0;q<16;q++){
            float4 av =*(const float4*)&Ab[q*64 + ty*4];
            float4 bv0=*(const float4*)&Bb[q*128 + tx*8];
            float4 bv1=*(const float4*)&Bb[q*128 + tx*8 + 4];
            c[0][0]+=av.x*bv0.x; c[0][1]+=av.x*bv0.y; c[0][2]+=av.x*bv0.z; c[0][3]+=av.x*bv0.w;
            c[0][4]+=av.x*bv1.x; c[0][5]+=av.x*bv1.y; c[0][6]+=av.x*bv1.z; c[0][7]+=av.x*bv1.w;
            c[1][0]+=av.y*bv0.x; c[1][1]+=av.y*bv0.y; c[1][2]+=av.y*bv0.z; c[1][3]+=av.y*bv0.w;
            c[1][4]+=av.y*bv1.x; c[1][5]+=av.y*bv1.y; c[1][6]+=av.y*bv1.z; c[1][7]+=av.y*bv1.w;
            c[2][0]+=av.z*bv0.x; c[2][1]+=av.z*bv0.y; c[2][2]+=av.z*bv0.z; c[2][3]+=av.z*bv0.w;
            c[2][4]+=av.z*bv1.x; c[2][5]+=av.z*bv1.y; c[2][6]+=av.z*bv1.z; c[2][7]+=av.z*bv1.w;
            c[3][0]+=av.w*bv0.x; c[3][1]+=av.w*bv0.y; c[3][2]+=av.w*bv0.z; c[3][3]+=av.w*bv0.w;
            c[3][4]+=av.w*bv1.x; c[3][5]+=av.w*bv1.y; c[3][6]+=av.w*bv1.z; c[3][7]+=av.w*bv1.w;
        }
        __syncthreads();
    }
    float* Pb=P+((size_t)z*64)*N + n0;
    #pragma unroll
    for(int i=0;i<4;i++){
        int m=ty*4+i;
        #pragma unroll
        for(int j=0;j<8;j++){
            int n=tx*8+j;
            if(n0+n<N) Pb[(size_t)m*N+n]=c[i][j];
        }
    }
}

__device__ void unit_crossatt(int b,int h,const float* __restrict__ beff,
                              float* __restrict__ pre2,float* sm){
    float* q2s=sm;          // 64
    float* ws =sm+64;       // 196
    float* os =sm+260;      // 256
    float* red=sm+520;      // 33
    const int tid=threadIdx.x;
    __syncthreads();
    if(tid<64){
        float a=beff[h*64+tid];
        #pragma unroll
        for(int z=0;z<16;z++) a+=g_Pq[((size_t)z*64+b)*DI + h*64+tid];
        q2s[tid]=a;
    }
    __syncthreads();
    float sv=-1e30f;
    if(tid<S_){
        const float* kr=g_KV+((size_t)(b*S_+tid))*DM + h*64;
        float a=0.f;
        #pragma unroll 8
        for(int dd=0;dd<64;dd++) a+=q2s[dd]*kr[dd];
        sv=a*0.125f;
    }
    float mxv=blockMax(sv,red);
    float ev=(tid<S_)?fexp(sv-mxv):0.f;
    float Z=blockSum(ev,red);
    if(tid<S_) ws[tid]=ev/Z;
    __syncthreads();
    int dd=tid&63, part=tid>>6;
    float acc=0.f;
    for(int s=part*49;s<part*49+49;s++)
        acc+=ws[s]*g_KV[((size_t)(b*S_+s))*DM + DI + h*64 + dd];
    os[part*64+dd]=acc;
    __syncthreads();
    if(tid<64)
        pre2[(size_t)b*1536 + h*64 + tid]=os[tid]+os[64+tid]+os[128+tid]+os[192+tid];
}

__device__ void unit_pred(int b,const float* __restrict__ ob,
                          float* __restrict__ out,int t,float* sm){
    float* pv=sm;           // 1000
    float* red=sm+1000;     // 33
    const int tid=threadIdx.x;
    __syncthreads();
    float lmax=-1e30f;
    for(int j=tid;j<OUTN;j+=256){
        float v=ob[j];
        const float* p=g_Po+(size_t)b*OUTN + j;
        #pragma unroll
        for(int z=0;z<16;z++){ v+=p[0]; p+=(size_t)64*OUTN; }
        pv[j]=v;
        out[((size_t)b*OUTN+j)*ITERS+t]=v;
        lmax=fmaxf(lmax,v);
    }
    float mx=blockMax(lmax,red);
    float lz=0.f, ls1=0.f;
    for(int j=tid;j<OUTN;j+=256){
        float e=fexp(pv[j]-mx);
        lz+=e; ls1+=e*pv[j];
    }
    float Z=blockSum(lz,red);
    float S1=blockSum(ls1,red);
    if(tid==0){
        float logZ=logf(Z);
        float plogp=S1/Z - mx - logZ;
        float ne=-plogp*(1.f/logf((float)OUTN));
        out[OFF_CERT + ((size_t)b*2+0)*ITERS + t]=ne;
        out[OFF_CERT + ((size_t)b*2+1)*ITERS + t]=1.f-ne;
    }
}

__device__ void unit_synep(int b,const float* __restrict__ lns,
                           const float* __restrict__ lnb,int w,float* sm){
    float* vals=sm;         // 1024
    float* red=sm+1024;     // 33
    const int tid=threadIdx.x;
    __syncthreads();
    float s=0.f, sq=0.f;
    #pragma unroll
    for(int r=0;r<4;r++){
        int j=tid+r*256;
        float a=g_bsyn[j], g=g_bsyn[DM+j];
        const float* p=g_Ps+(size_t)b*2048 + j;
        #pragma unroll
        for(int z=0;z<16;z++){
            a+=p[0]; g+=p[DM];
            p+=(size_t)64*2048;
        }
        float v=a*sigm(g);
        vals[j]=v; s+=v; sq+=v*v;
    }
    s=blockSum(s,red); sq=blockSum(sq,red);
    float mean=s*(1.f/DM);
    float var=sq*(1.f/DM)-mean*mean;
    float rstd=rsqrtf(var+1e-5f);
    #pragma unroll
    for(int r=0;r<4;r++){
        int j=tid+r*256;
        g_st[((size_t)w*DM + j)*B_ + b]=(vals[j]-mean)*rstd*lns[j]+lnb[j];
    }
}

__device__ void unit_nlm(int u,const float* __restrict__ w1,const float* __restrict__ b1,
                         const float* __restrict__ w2,const float* __restrict__ b2,
                         int t,float* sm){
    float* w1s=sm;          // 3200
    float* b1s=sm+3200;     // 128
    float* w2s=sm+3328;     // 128
    float* b2s=sm+3456;     // 8
    const int tid=threadIdx.x, d0=u*4;
    __syncthreads();
    for(int i=tid;i<MEMN*32*4;i+=256){
        int m=i>>7, r=i&127, j=r>>2, dl=r&3;
        w1s[i]=w1[(size_t)(m*32+j)*DM + d0+dl];
    }
    if(tid<128){ int j=tid>>2, dl=tid&3; b1s[tid]=b1[(d0+dl)*32+j]; }
    else {
        int i=tid-128; int hh=i>>3, o=(i>>2)&1, dl=i&3;
        w2s[i]=w2[(size_t)(hh*2+o)*DM + d0+dl];
    }
    if(tid<8){ int o=tid>>2, dl=tid&3; b2s[tid]=b2[(d0+dl)*2+o]; }
    __syncthreads();
    int b=tid&63, dl=tid>>6, d=d0+dl;
    float stv[MEMN];
    #pragma unroll
    for(int m=0;m<MEMN;m++){
        int phys=(t+1+m)%MEMN;
        stv[m]=g_st[((size_t)phys*DM + d)*B_ + b];
    }
    float o0=0.f,o1=0.f;
    #pragma unroll
    for(int j=0;j<16;j++){
        float a=b1s[j*4+dl], g=b1s[(j+16)*4+dl];
        #pragma unroll
        for(int m=0;m<MEMN;m++){
            a+=stv[m]*w1s[(m*32+j)*4+dl];
            g+=stv[m]*w1s[(m*32+j+16)*4+dl];
        }
        float hv=a*sigm(g);
        o0+=hv*w2s[(j*2+0)*4+dl];
        o1+=hv*w2s[(j*2+1)*4+dl];
    }
    o0+=b2s[0*4+dl]; o1+=b2s[1*4+dl];
    float v=o0*sigm(o1);
    g_act[b*DM+d]=v;
    g_pre2[(size_t)b*1536 + 512 + d]=v;
}

// sync attention with cached score matrix + rank-1 delta update
__device__ void unit_sync(int b,int h,int slot,int initAll,
                          float* __restrict__ outOpt,float* sm){
    float* qn=sm;           // 128
    float* kn=sm+128;       // 128
    float* vn=sm+256;       // 128
    float* qo=sm+384;       // 128
    float* ko=sm+512;       // 128
    float* red =sm+640;     // 256
    float* red2=sm+896;     // 256
    const int tid=threadIdx.x;
    __syncthreads();
    if(tid<128){
        int col=h*128+tid;
        float v=0.f;
        const float* p=g_Pk+(size_t)b*3072+col;
        #pragma unroll
        for(int z=0;z<16;z++){ v+=*p; p+=(size_t)64*3072; }
        qn[tid]=v;
        qo[tid]= initAll?0.f:g_Qb[(b*MEMN+slot)*DM+col];
        if(initAll){
            #pragma unroll
            for(int m=0;m<MEMN;m++) g_Qb[(b*MEMN+m)*DM+col]=v;
        } else g_Qb[(b*MEMN+slot)*DM+col]=v;
    } else {
        int e=tid-128, col=h*128+e;
        float k=0.f, vv=0.f;
        const float* p=g_Pk+(size_t)b*3072+col;
        #pragma unroll
        for(int z=0;z<16;z++){ k+=p[1024]; vv+=p[2048]; p+=(size_t)64*3072; }
        kn[e]=k; vn[e]=vv;
        ko[e]= initAll?0.f:g_Kb[(b*MEMN+slot)*DM+col];
        if(initAll){
            #pragma unroll
            for(int m=0;m<MEMN;m++) g_Kb[(b*MEMN+m)*DM+col]=k;
        } else g_Kb[(b*MEMN+slot)*DM+col]=k;
    }
    __syncthreads();
    int d=tid&127, half=tid>>7;
    float* Sp = g_S + (((size_t)(b*8+h))*128 + d)*128 + half*64;
    float qnd=qn[d], qod=qo[d];
    const float* kns=kn+half*64;
    const float* kos=ko+half*64;
    float lmax=-1e30f;
    if(initAll){
        #pragma unroll 8
        for(int e=0;e<64;e++){
            float s=25.f*qnd*kns[e];
            Sp[e]=s;
            lmax=fmaxf(lmax,s);
        }
    }else{
        #pragma unroll 8
        for(int e=0;e<64;e++){
            float s=Sp[e]+qnd*kns[e]-qod*kos[e];
            Sp[e]=s;
            lmax=fmaxf(lmax,s);
        }
    }
    red[tid]=lmax;
    __syncthreads();
    float rm=fmaxf(red[d],red[d+128]);
    const float sc=0.08838834764831845f;   // 1/sqrt(128)
    float Z=0.f, acc=0.f;
    const float* vns=vn+half*64;
    #pragma unroll 8
    for(int e=0;e<64;e++){
        float w=fexp((Sp[e]-rm)*sc);
        Z+=w; acc+=w*vns[e];
    }
    __syncthreads();
    red[tid]=Z; red2[tid]=acc;
    __syncthreads();
    if(tid<128){
        float att=(red2[tid]+red2[tid+128])/(red[tid]+red[tid+128]);
        g_sync[b*DM + tid*8 + h]=att;
        if(outOpt) outOpt[b*DM + tid*8 + h]=att;
    }
}

// ======================= the megakernel =====================================
__global__ void __launch_bounds__(256,2) k_mega(
    const float* __restrict__ beff,
    const float* __restrict__ slns, const float* __restrict__ slnb,
    const float* __restrict__ w1, const float* __restrict__ b1,
    const float* __restrict__ w2, const float* __restrict__ b2,
    const float* __restrict__ outw, const float* __restrict__ outb,
    float* __restrict__ out)
{
    __shared__ float sm[6144];
    unsigned target=0;

    // pre-loop: QKV of initial activation (24n x 16z = 384 units), init S + rings
    for(int u=blockIdx.x; u<384; u+=NB)
        unit_gemm2(g_act, g_Wqkv, g_Pk, 3*DM, DM, (u%24)*128, u/24, 4, sm);
    gsync(target);
    for(int u=blockIdx.x; u<512; u+=NB)
        unit_sync(u>>3, u&7, 0, 1, nullptr, sm);
    gsync(target);

    for(int t=0;t<ITERS;t++){
        // P1: cross-Q GEMM (4n x 16z = 64) + output-head GEMM for t-1 (8n x 16z = 128)
        int nU1 = (t==0)?64:192;
        for(int u=blockIdx.x; u<nU1; u+=NB){
            if(u<64) unit_gemm2(g_sync, g_Mq, g_Pq, DI, DM, (u&3)*128, u>>2, 4, sm);
            else { int v=u-64; unit_gemm2(g_sync, outw, g_Po, OUTN, DM, (v&7)*128, v>>3, 4, sm); }
        }
        gsync(target);
        // P2: cross attention (512) + pred for t-1 (64)
        int nU2 = (t==0)?512:576;
        for(int u=blockIdx.x; u<nU2; u+=NB){
            if(u<512) unit_crossatt(u>>3, u&7, beff, g_pre2, sm);
            else unit_pred(u-512, outb, out, t-1, sm);
        }
        gsync(target);
        // P3: synapse GEMM 64x2048x1536 (16n x 16z, K slab 96)
        for(int u=blockIdx.x; u<256; u+=NB)
            unit_gemm2(g_pre2, g_synw2, g_Ps, 2048, 1536, (u&15)*128, u>>4, 6, sm);
        gsync(target);
        // P4: GLU+LN -> trace slot
        for(int u=blockIdx.x; u<64; u+=NB)
            unit_synep(u, slns, slnb, t%MEMN, sm);
        gsync(target);
        // P5: per-neuron NLM
        for(int u=blockIdx.x; u<256; u+=NB)
            unit_nlm(u, w1, b1, w2, b2, t, sm);
        gsync(target);
        // P6: QKV projection of new activation (24n x 16z = 384)
        for(int u=blockIdx.x; u<384; u+=NB)
            unit_gemm2(g_act, g_Wqkv, g_Pk, 3*DM, DM, (u%24)*128, u/24, 4, sm);
        gsync(target);
        // P7: sync attention (delta update + softmax + AV)
        for(int u=blockIdx.x; u<512; u+=NB)
            unit_sync(u>>3, u&7, t%MEMN, 0,
                      (t==ITERS-1)?(out+OFF_SYNC):nullptr, sm);
        gsync(target);
    }
    // tail: output head + pred for tick 49
    for(int u=blockIdx.x; u<128; u+=NB)
        unit_gemm2(g_sync, outw, g_Po, OUTN, DM, (u&7)*128, u>>3, 4, sm);
    gsync(target);
    for(int u=blockIdx.x; u<64; u+=NB)
        unit_pred(u, outb, out, ITERS-1, sm);
}

// ------------------------- host driver -------------------------------------
extern "C" void kernel_launch(void* const* d_in, const int* in_sizes, int n_in,
                              void* d_out, int out_size){
    (void)in_sizes; (void)n_in; (void)out_size;
    const float* x    =(const float*)d_in[0];
    const float* kv_w =(const float*)d_in[1];
    const float* kv_b =(const float*)d_in[2];
    const float* lnks =(const float*)d_in[3];
    const float* lnkb =(const float*)d_in[4];
    const float* q_w  =(const float*)d_in[5];
    const float* q_b  =(const float*)d_in[6];
    const float* inw  =(const float*)d_in[7];
    const float* inb  =(const float*)d_in[8];
    const float* opw  =(const float*)d_in[9];
    const float* opb  =(const float*)d_in[10];
    const float* Wq   =(const float*)d_in[11];
    const float* Wk   =(const float*)d_in[12];
    const float* Wv   =(const float*)d_in[13];
    const float* synw =(const float*)d_in[14];
    const float* synb =(const float*)d_in[15];
    const float* slns =(const float*)d_in[16];
    const float* slnb =(const float*)d_in[17];
    const float* w1   =(const float*)d_in[18];
    const float* b1   =(const float*)d_in[19];
    const float* w2   =(const float*)d_in[20];
    const float* b2   =(const float*)d_in[21];
    const float* sas  =(const float*)d_in[22];
    const float* strc =(const float*)d_in[23];
    const float* outw =(const float*)d_in[24];
    const float* outb =(const float*)d_in[25];
    float* out=(float*)d_out;

    float *p_kv,*p_KV,*p_W,*p_Mq,*p_beff,*p_synw2,*p_bsyn,*p_act,*p_pre2,*p_st;
    unsigned* p_bar;
    cudaGetSymbolAddress((void**)&p_kv,   g_kv);
    cudaGetSymbolAddress((void**)&p_KV,   g_KV);
    cudaGetSymbolAddress((void**)&p_W,    g_Wqkv);
    cudaGetSymbolAddress((void**)&p_Mq,   g_Mq);
    cudaGetSymbolAddress((void**)&p_beff, g_beff);
    cudaGetSymbolAddress((void**)&p_synw2,g_synw2);
    cudaGetSymbolAddress((void**)&p_bsyn, g_bsyn);
    cudaGetSymbolAddress((void**)&p_act,  g_act);
    cudaGetSymbolAddress((void**)&p_pre2, g_pre2);
    cudaGetSymbolAddress((void**)&p_st,   g_st);
    cudaGetSymbolAddress((void**)&p_bar,  g_barCnt);

    // ---- setup: folded weights + KV cache ----
    k_copyW<<<(3*DM*DM+255)/256,256>>>(Wq,Wk,Wv,p_W);
    k_initact<<<(B_*DM+255)/256,256>>>(sas,p_act,p_pre2);
    k_initst<<<(MEMN*DM*B_+255)/256,256>>>(strc,p_st);
    k_gemm<<<dim3(DI/64,MS/64,1),256>>>(x,kv_w,p_KV,nullptr,MS,DI,DI,DI);
    k_lnkv<<<MS,256>>>(p_KV,kv_b,lnks,lnkb,p_kv);
    k_gemm<<<dim3(DM/64,MS/64,1),256>>>(p_kv,inw+(size_t)DI*DI,p_KV,inb+DI,MS,DM,DI,DI);
    k_gemm_tn<<<dim3(DM/64,DI/64),256>>>(inw,q_w,p_Mq,DI,DM,DM,DI,0);
    k_gemm_tn<<<dim3(DI/64,2048/64),256>>>(synw,opw,p_synw2,1536,DI,1536,DI,0);
    k_copyW2<<<(2048*1024+255)/256,256>>>(synw,p_synw2);
    k_bvec<<<2,256>>>(inw,DI,DI,q_b,inb,p_beff,DI);
    k_bvec<<<8,256>>>(synw,1536,DI,opb,synb,p_bsyn,2048);
    // ---- megakernel: all 50 ticks ----
    k_zero<<<1,32>>>(p_bar);
    k_mega<<<NB,256>>>(p_beff,slns,slnb,w1,b1,w2,b2,outw,outb,out);
}

// round 14
// speedup vs baseline: 1.6156x; 1.0350x over previous
#include <cuda_runtime.h>
#include <math.h>

#define B_    64
#define S_    196
#define DM    1024
#define DI    512
#define MEMN  25
#define ITERS 50
#define OUTN  1000
#define MS    (B_*S_)
#define NB    256

#define OFF_CERT (B_*OUTN*ITERS)
#define OFF_SYNC (OFF_CERT + B_*2*ITERS)

// ------------------------- device scratch ----------------------------------
__device__ __align__(16) float g_kv   [MS*DI];
__device__ __align__(16) float g_KV   [MS*DM];
__device__ __align__(16) float g_Wqkv [3*DM*DM];
__device__ __align__(16) float g_Mq   [DI*DM];
__device__ __align__(16) float g_beff [DI];
__device__ __align__(16) float g_synw2[2048*1536];
__device__ __align__(16) float g_bsyn [2048];
__device__ __align__(16) float g_Qb   [B_*MEMN*DM];
__device__ __align__(16) float g_Kb   [B_*MEMN*DM];
__device__ __align__(16) float g_st   [MEMN*DM*B_];
__device__ __align__(16) float g_act  [B_*DM];
__device__ __align__(16) float g_sync [B_*DM];
__device__ __align__(16) float g_pre2 [B_*1536];
__device__ __align__(16) float g_S    [B_*8*128*128];   // cached sync scores
__device__ __align__(16) float g_Pq   [16*B_*DI];
__device__ __align__(16) float g_Po   [16*B_*OUTN];
__device__ __align__(16) float g_Ps   [16*B_*2048];
__device__ __align__(16) float g_Pk   [16*B_*3*DM];
__device__ unsigned g_barCnt;

// ------------------------- fast exp (FMA pipe, not MUFU) -------------------
__device__ __forceinline__ float fexp(float x){
    x = fminf(fmaxf(x,-80.f),80.f);
    float y = x*1.442695041f;
    float n = rintf(y);
    float f = y - n;
    float p = 1.3333558e-3f;
    p = fmaf(p,f,9.6181250e-3f);
    p = fmaf(p,f,5.5504110e-2f);
    p = fmaf(p,f,2.4022650e-1f);
    p = fmaf(p,f,6.9314718e-1f);
    p = fmaf(p,f,1.0f);
    return __int_as_float(__float_as_int(p) + (((int)n)<<23));
}
__device__ __forceinline__ float sigm(float x){ return 1.f/(1.f+fexp(-x)); }

// ------------------------- reductions --------------------------------------
__device__ __forceinline__ float warpSum(float v){
    #pragma unroll
    for(int o=16;o;o>>=1) v += __shfl_down_sync(0xffffffffu,v,o);
    return v;
}
__device__ __forceinline__ float warpMax(float v){
    #pragma unroll
    for(int o=16;o;o>>=1) v = fmaxf(v,__shfl_down_sync(0xffffffffu,v,o));
    return v;
}
__device__ float blockSum(float v, float* buf){
    int lane=threadIdx.x&31, w=threadIdx.x>>5, nw=(blockDim.x+31)>>5;
    v=warpSum(v);
    if(lane==0) buf[w]=v;
    __syncthreads();
    v=(threadIdx.x<nw)?buf[threadIdx.x]:0.f;
    if(w==0) v=warpSum(v);
    if(threadIdx.x==0) buf[0]=v;
    __syncthreads();
    float r=buf[0]; __syncthreads(); return r;
}
__device__ float blockMax(float v, float* buf){
    int lane=threadIdx.x&31, w=threadIdx.x>>5, nw=(blockDim.x+31)>>5;
    v=warpMax(v);
    if(lane==0) buf[w]=v;
    __syncthreads();
    v=(threadIdx.x<nw)?buf[threadIdx.x]:-1e30f;
    if(w==0) v=warpMax(v);
    if(threadIdx.x==0) buf[0]=v;
    __syncthreads();
    float r=buf[0]; __syncthreads(); return r;
}

// ------------------------- grid barrier ------------------------------------
__device__ __forceinline__ void gsync(unsigned &target){
    __threadfence();
    __syncthreads();
    target += NB;
    if(threadIdx.x==0){
        atomicAdd(&g_barCnt,1u);
        while(*(volatile unsigned*)&g_barCnt < target) __nanosleep(64);
        __threadfence();
    }
    __syncthreads();
}

// ------------------------- setup: split-K SGEMM ----------------------------
__global__ void __launch_bounds__(256) k_gemm(const float* __restrict__ A,
                                              const float* __restrict__ W,
                                              float* __restrict__ P,
                                              const float* __restrict__ bias,
                                              int M,int N,int K,int kchunk){
    __shared__ float As[16][64];
    __shared__ float Ws[16][64];
    const int n0=blockIdx.x*64, m0=blockIdx.y*64, k0=blockIdx.z*kchunk;
    const int tid=threadIdx.x;
    const int tx=tid&15, ty=tid>>4;
    const int lr=tid>>2, lc=tid&3;
    float c[4][4];
    #pragma unroll
    for(int i=0;i<4;i++){c[i][0]=0;c[i][1]=0;c[i][2]=0;c[i][3]=0;}
    const float* Ab = A + (size_t)(m0+lr)*K + k0 + lc*4;
    const bool wok = (n0+lr)<N;
    const float* Wb = W + (size_t)(n0+lr)*K + k0 + lc*4;
    for(int kk=0; kk<kchunk; kk+=16){
        float4 av = *(const float4*)(Ab+kk);
        float4 wv = wok ? *(const float4*)(Wb+kk) : make_float4(0,0,0,0);
        __syncthreads();
        As[lc*4+0][lr]=av.x; As[lc*4+1][lr]=av.y; As[lc*4+2][lr]=av.z; As[lc*4+3][lr]=av.w;
        Ws[lc*4+0][lr]=wv.x; Ws[lc*4+1][lr]=wv.y; Ws[lc*4+2][lr]=wv.z; Ws[lc*4+3][lr]=wv.w;
        __syncthreads();
        #pragma unroll
        for(int q=0;q<16;q++){
            float4 a=*(const float4*)&As[q][ty*4];
            float4 w=*(const float4*)&Ws[q][tx*4];
            c[0][0]+=a.x*w.x; c[0][1]+=a.x*w.y; c[0][2]+=a.x*w.z; c[0][3]+=a.x*w.w;
            c[1][0]+=a.y*w.x; c[1][1]+=a.y*w.y; c[1][2]+=a.y*w.z; c[1][3]+=a.y*w.w;
            c[2][0]+=a.z*w.x; c[2][1]+=a.z*w.y; c[2][2]+=a.z*w.z; c[2][3]+=a.z*w.w;
            c[3][0]+=a.w*w.x; c[3][1]+=a.w*w.y; c[3][2]+=a.w*w.z; c[3][3]+=a.w*w.w;
        }
    }
    float* Pb = P + ((size_t)blockIdx.z*M + m0)*N + n0;
    #pragma unroll
    for(int i=0;i<4;i++){
        int m=ty*4+i;
        #pragma unroll
        for(int j=0;j<4;j++){
            int n=tx*4+j;
            if(n0+n<N){
                float v=c[i][j];
                if(bias) v+=bias[n0+n];
                Pb[(size_t)m*N+n]=v;
            }
        }
    }
}

// ------------------------- setup: TN GEMM C = A(MxK)@B(KxN) ----------------
__global__ void __launch_bounds__(256) k_gemm_tn(const float* __restrict__ A,
                                                 const float* __restrict__ B,
                                                 float* __restrict__ C,
                                                 int lda,int ldb,int ldc,int K,int transC){
    __shared__ float As[16][64];
    __shared__ float Bs[16][64];
    const int n0=blockIdx.x*64, m0=blockIdx.y*64;
    const int tid=threadIdx.x;
    const int tx=tid&15, ty=tid>>4;
    const int lr=tid>>2, lc=tid&3;
    const int br=tid>>4, bc=(tid&15)*4;
    float c[4][4];
    #pragma unroll
    for(int i=0;i<4;i++){c[i][0]=0;c[i][1]=0;c[i][2]=0;c[i][3]=0;}
    for(int k0=0;k0<K;k0+=16){
        float4 av=*(const float4*)(A+(size_t)(m0+lr)*lda + k0 + lc*4);
        float4 bv=*(const float4*)(B+(size_t)(k0+br)*ldb + n0 + bc);
        __syncthreads();
        As[lc*4+0][lr]=av.x; As[lc*4+1][lr]=av.y; As[lc*4+2][lr]=av.z; As[lc*4+3][lr]=av.w;
        *(float4*)&Bs[br][bc]=bv;
        __syncthreads();
        #pragma unroll
        for(int q=0;q<16;q++){
            float4 a=*(const float4*)&As[q][ty*4];
            float4 w=*(const float4*)&Bs[q][tx*4];
            c[0][0]+=a.x*w.x; c[0][1]+=a.x*w.y; c[0][2]+=a.x*w.z; c[0][3]+=a.x*w.w;
            c[1][0]+=a.y*w.x; c[1][1]+=a.y*w.y; c[1][2]+=a.y*w.z; c[1][3]+=a.y*w.w;
            c[2][0]+=a.z*w.x; c[2][1]+=a.z*w.y; c[2][2]+=a.z*w.z; c[2][3]+=a.z*w.w;
            c[3][0]+=a.w*w.x; c[3][1]+=a.w*w.y; c[3][2]+=a.w*w.z; c[3][3]+=a.w*w.w;
        }
    }
    #pragma unroll
    for(int i=0;i<4;i++){
        #pragma unroll
        for(int j=0;j<4;j++){
            int m=m0+ty*4+i, n=n0+tx*4+j;
            if(transC) C[(size_t)n*ldc+m]=c[i][j];
            else       C[(size_t)m*ldc+n]=c[i][j];
        }
    }
}

// ------------------------- setup small kernels ------------------------------
__global__ void k_copyW(const float* __restrict__ wq,const float* __restrict__ wk,
                        const float* __restrict__ wv,float* __restrict__ dst){
    int i=blockIdx.x*blockDim.x+threadIdx.x;
    if(i>=3*DM*DM) return;
    int part=i/(DM*DM), r=i%(DM*DM);
    dst[i]=(part==0)?wq[r]:(part==1)?wk[r]:wv[r];
}
__global__ void k_copyW2(const float* __restrict__ synw,float* __restrict__ dst){
    int i=blockIdx.x*blockDim.x+threadIdx.x;
    if(i>=2048*1024) return;
    int m=i>>10, k=i&1023;
    dst[(size_t)m*1536+512+k]=synw[(size_t)m*1536+512+k];
}
__global__ void k_initact(const float* __restrict__ sas,float* __restrict__ act,
                          float* __restrict__ pre2){
    int i=blockIdx.x*blockDim.x+threadIdx.x;
    if(i>=B_*DM) return;
    float v=sas[i&(DM-1)];
    act[i]=v;
    pre2[(size_t)(i>>10)*1536 + 512 + (i&(DM-1))]=v;
}
__global__ void k_initst(const float* __restrict__ strace,float* __restrict__ st){
    int i=blockIdx.x*blockDim.x+threadIdx.x;
    if(i>=MEMN*DM*B_) return;
    int slot=i/(DM*B_), r=i%(DM*B_), d=r/B_;
    st[i]=strace[d*MEMN+slot];
}
__global__ void k_lnkv(const float* __restrict__ tmp,const float* __restrict__ kvb,
                       const float* __restrict__ lns,const float* __restrict__ lnb,
                       float* __restrict__ kv){
    __shared__ float red[33];
    int r=blockIdx.x, tid=threadIdx.x;
    float v0=tmp[r*DI+tid]+kvb[tid];
    float v1=tmp[r*DI+tid+256]+kvb[tid+256];
    float s=blockSum(v0+v1,red);
    float sq=blockSum(v0*v0+v1*v1,red);
    float mean=s*(1.f/DI);
    float var=sq*(1.f/DI)-mean*mean;
    float rstd=rsqrtf(var+1e-5f);
    kv[r*DI+tid]    =(v0-mean)*rstd*lns[tid]    +lnb[tid];
    kv[r*DI+tid+256]=(v1-mean)*rstd*lns[tid+256]+lnb[tid+256];
}
__global__ void k_bvec(const float* __restrict__ W,int lda,int K,
                       const float* __restrict__ v,const float* __restrict__ b0,
                       float* __restrict__ o,int n){
    int i=blockIdx.x*blockDim.x+threadIdx.x;
    if(i>=n) return;
    float a=b0[i];
    const float* wr=W+(size_t)i*lda;
    for(int k=0;k<K;k++) a+=wr[k]*v[k];
    o[i]=a;
}
__global__ void k_zero(unsigned* p){ if(threadIdx.x==0) *p=0; }

// ======================= megakernel phase workers ===========================
// 64x128 tile, double-buffered, 4x8 micro. K slab = ksteps*16 at slab z.
__device__ void unit_gemm2(const float* __restrict__ A,const float* __restrict__ W,
                           float* __restrict__ P,int N,int Ksrc,
                           int n0,int z,int ksteps,float* sm){
    float* As=sm;          // [2][16][64]
    float* Bs=sm+2048;     // [2][16][128]
    const int tid=threadIdx.x;
    const int tx=tid&15, ty=tid>>4;
    const int ar=tid>>2, ac=(tid&3)*4;
    const int br=tid>>1, bc=(tid&1)*8;
    const int k0=z*ksteps*16;
    const bool wok=(n0+br)<N;
    const float* Ap=A+(size_t)ar*Ksrc + k0 + ac;
    const float* Wp=W+(size_t)(n0+br)*Ksrc + k0 + bc;
    float c[4][8];
    #pragma unroll
    for(int i=0;i<4;i++)
        #pragma unroll
        for(int j=0;j<8;j++) c[i][j]=0.f;
    float4 a=*(const float4*)Ap;
    float4 b0=wok?*(const float4*)Wp:make_float4(0,0,0,0);
    float4 b1=wok?*(const float4*)(Wp+4):make_float4(0,0,0,0);
    __syncthreads();                       // drain previous unit's smem reads
    for(int s=0;s<ksteps;s++){
        int buf=s&1;
        float* Ab=As+buf*1024;
        float* Bb=Bs+buf*2048;
        Ab[(ac+0)*64+ar]=a.x; Ab[(ac+1)*64+ar]=a.y;
        Ab[(ac+2)*64+ar]=a.z; Ab[(ac+3)*64+ar]=a.w;
        Bb[(bc+0)*128+br]=b0.x; Bb[(bc+1)*128+br]=b0.y;
        Bb[(bc+2)*128+br]=b0.z; Bb[(bc+3)*128+br]=b0.w;
        Bb[(bc+4)*128+br]=b1.x; Bb[(bc+5)*128+br]=b1.y;
        Bb[(bc+6)*128+br]=b1.z; Bb[(bc+7)*128+br]=b1.w;
        __syncthreads();
        if(s+1<ksteps){
            a=*(const float4*)(Ap+(s+1)*16);
            b0=wok?*(const float4*)(Wp+(s+1)*16):make_float4(0,0,0,0);
            b1=wok?*(const float4*)(Wp+(s+1)*16+4):make_float4(0,0,0,0);
        }
        #pragma unroll
        for(int q=0;q<16;q++){
            float4 av =*(const float4*)&Ab[q*64 + ty*4];
            float4 bv0=*(const float4*)&Bb[q*128 + tx*8];
            float4 bv1=*(const float4*)&Bb[q*128 + tx*8 + 4];
            c[0][0]+=av.x*bv0.x; c[0][1]+=av.x*bv0.y; c[0][2]+=av.x*bv0.z; c[0][3]+=av.x*bv0.w;
            c[0][4]+=av.x*bv1.x; c[0][5]+=av.x*bv1.y; c[0][6]+=av.x*bv1.z; c[0][7]+=av.x*bv1.w;
            c[1][0]+=av.y*bv0.x; c[1][1]+=av.y*bv0.y; c[1][2]+=av.y*bv0.z; c[1][3]+=av.y*bv0.w;
            c[1][4]+=av.y*bv1.x; c[1][5]+=av.y*bv1.y; c[1][6]+=av.y*bv1.z; c[1][7]+=av.y*bv1.w;
            c[2][0]+=av.z*bv0.x; c[2][1]+=av.z*bv0.y; c[2][2]+=av.z*bv0.z; c[2][3]+=av.z*bv0.w;
            c[2][4]+=av.z*bv1.x; c[2][5]+=av.z*bv1.y; c[2][6]+=av.z*bv1.z; c[2][7]+=av.z*bv1.w;
            c[3][0]+=av.w*bv0.x; c[3][1]+=av.w*bv0.y; c[3][2]+=av.w*bv0.z; c[3][3]+=av.w*bv0.w;
            c[3][4]+=av.w*bv1.x; c[3][5]+=av.w*bv1.y; c[3][6]+=av.w*bv1.z; c[3][7]+=av.w*bv1.w;
        }
        __syncthreads();
    }
    float* Pb=P+((size_t)z*64)*N + n0;
    #pragma unroll
    for(int i=0;i<4;i++){
        int m=ty*4+i;
        #pragma unroll
        for(int j=0;j<8;j++){
            int n=tx*8+j;
            if(n0+n<N) Pb[(size_t)m*N+n]=c[i][j];
        }
    }
}

__device__ void unit_crossatt(int b,int h,const float* __restrict__ beff,
                              float* __restrict__ pre2,float* sm){
    float* q2s=sm;          // 64
    float* ws =sm+64;       // 196
    float* os =sm+260;      // 256
    float* red=sm+520;      // 33
    const int tid=threadIdx.x;
    __syncthreads();
    if(tid<64){
        float a=beff[h*64+tid];
        #pragma unroll
        for(int z=0;z<16;z++) a+=g_Pq[((size_t)z*64+b)*DI + h*64+tid];
        q2s[tid]=a;
    }
    __syncthreads();
    float sv=-1e30f;
    if(tid<S_){
        const float* kr=g_KV+((size_t)(b*S_+tid))*DM + h*64;
        float a=0.f;
        #pragma unroll 8
        for(int dd=0;dd<64;dd++) a+=q2s[dd]*kr[dd];
        sv=a*0.125f;
    }
    float mxv=blockMax(sv,red);
    float ev=(tid<S_)?fexp(sv-mxv):0.f;
    float Z=blockSum(ev,red);
    if(tid<S_) ws[tid]=ev/Z;
    __syncthreads();
    int dd=tid&63, part=tid>>6;
    float acc=0.f;
    for(int s=part*49;s<part*49+49;s++)
        acc+=ws[s]*g_KV[((size_t)(b*S_+s))*DM + DI + h*64 + dd];
    os[part*64+dd]=acc;
    __syncthreads();
    if(tid<64)
        pre2[(size_t)b*1536 + h*64 + tid]=os[tid]+os[64+tid]+os[128+tid]+os[192+tid];
}

__device__ void unit_pred(int b,const float* __restrict__ ob,
                          float* __restrict__ out,int t,float* sm){
    float* pv=sm;           // 1000
    float* red=sm+1000;     // 33
    const int tid=threadIdx.x;
    __syncthreads();
    float lmax=-1e30f;
    for(int j=tid;j<OUTN;j+=256){
        float v=ob[j];
        const float* p=g_Po+(size_t)b*OUTN + j;
        #pragma unroll
        for(int z=0;z<16;z++){ v+=p[0]; p+=(size_t)64*OUTN; }
        pv[j]=v;
        out[((size_t)b*OUTN+j)*ITERS+t]=v;
        lmax=fmaxf(lmax,v);
    }
    float mx=blockMax(lmax,red);
    float lz=0.f, ls1=0.f;
    for(int j=tid;j<OUTN;j+=256){
        float e=fexp(pv[j]-mx);
        lz+=e; ls1+=e*pv[j];
    }
    float Z=blockSum(lz,red);
    float S1=blockSum(ls1,red);
    if(tid==0){
        float logZ=logf(Z);
        float plogp=S1/Z - mx - logZ;
        float ne=-plogp*(1.f/logf((float)OUTN));
        out[OFF_CERT + ((size_t)b*2+0)*ITERS + t]=ne;
        out[OFF_CERT + ((size_t)b*2+1)*ITERS + t]=1.f-ne;
    }
}

__device__ void unit_synep(int b,const float* __restrict__ lns,
                           const float* __restrict__ lnb,int w,float* sm){
    float* vals=sm;         // 1024
    float* red=sm+1024;     // 33
    const int tid=threadIdx.x;
    __syncthreads();
    float s=0.f, sq=0.f;
    #pragma unroll
    for(int r=0;r<4;r++){
        int j=tid+r*256;
        float a=g_bsyn[j], g=g_bsyn[DM+j];
        const float* p=g_Ps+(size_t)b*2048 + j;
        #pragma unroll
        for(int z=0;z<16;z++){
            a+=p[0]; g+=p[DM];
            p+=(size_t)64*2048;
        }
        float v=a*sigm(g);
        vals[j]=v; s+=v; sq+=v*v;
    }
    s=blockSum(s,red); sq=blockSum(sq,red);
    float mean=s*(1.f/DM);
    float var=sq*(1.f/DM)-mean*mean;
    float rstd=rsqrtf(var+1e-5f);
    #pragma unroll
    for(int r=0;r<4;r++){
        int j=tid+r*256;
        g_st[((size_t)w*DM + j)*B_ + b]=(vals[j]-mean)*rstd*lns[j]+lnb[j];
    }
}

__device__ void unit_nlm(int u,const float* __restrict__ w1,const float* __restrict__ b1,
                         const float* __restrict__ w2,const float* __restrict__ b2,
                         int t,float* sm){
    float* w1s=sm;          // 3200
    float* b1s=sm+3200;     // 128
    float* w2s=sm+3328;     // 128
    float* b2s=sm+3456;     // 8
    const int tid=threadIdx.x, d0=u*4;
    __syncthreads();
    for(int i=tid;i<MEMN*32*4;i+=256){
        int m=i>>7, r=i&127, j=r>>2, dl=r&3;
        w1s[i]=w1[(size_t)(m*32+j)*DM + d0+dl];
    }
    if(tid<128){ int j=tid>>2, dl=tid&3; b1s[tid]=b1[(d0+dl)*32+j]; }
    else {
        int i=tid-128; int hh=i>>3, o=(i>>2)&1, dl=i&3;
        w2s[i]=w2[(size_t)(hh*2+o)*DM + d0+dl];
    }
    if(tid<8){ int o=tid>>2, dl=tid&3; b2s[tid]=b2[(d0+dl)*2+o]; }
    __syncthreads();
    int b=tid&63, dl=tid>>6, d=d0+dl;
    float stv[MEMN];
    #pragma unroll
    for(int m=0;m<MEMN;m++){
        int phys=(t+1+m)%MEMN;
        stv[m]=g_st[((size_t)phys*DM + d)*B_ + b];
    }
    float o0=0.f,o1=0.f;
    #pragma unroll
    for(int j=0;j<16;j++){
        float a=b1s[j*4+dl], g=b1s[(j+16)*4+dl];
        #pragma unroll
        for(int m=0;m<MEMN;m++){
            a+=stv[m]*w1s[(m*32+j)*4+dl];
            g+=stv[m]*w1s[(m*32+j+16)*4+dl];
        }
        float hv=a*sigm(g);
        o0+=hv*w2s[(j*2+0)*4+dl];
        o1+=hv*w2s[(j*2+1)*4+dl];
    }
    o0+=b2s[0*4+dl]; o1+=b2s[1*4+dl];
    float v=o0*sigm(o1);
    g_act[b*DM+d]=v;
    g_pre2[(size_t)b*1536 + 512 + d]=v;
}

// sync attention: cached score matrix, rank-1 delta update, fused softmax+AV.
// Coalesced: warp w owns rows d in [w*16, w*16+16); lanes stride e by 32.
__device__ void unit_sync(int b,int h,int slot,int initAll,
                          float* __restrict__ outOpt,float* sm){
    float* qn=sm;           // 128
    float* kn=sm+128;       // 128
    float* vn=sm+256;       // 128
    float* qo=sm+384;       // 128
    float* ko=sm+512;       // 128
    const int tid=threadIdx.x;
    __syncthreads();
    if(tid<128){
        int col=h*128+tid;
        float v=0.f;
        const float* p=g_Pk+(size_t)b*3072+col;
        #pragma unroll
        for(int z=0;z<16;z++){ v+=*p; p+=(size_t)64*3072; }
        qn[tid]=v;
        qo[tid]= initAll?0.f:g_Qb[(b*MEMN+slot)*DM+col];
        if(initAll){
            #pragma unroll
            for(int m=0;m<MEMN;m++) g_Qb[(b*MEMN+m)*DM+col]=v;
        } else g_Qb[(b*MEMN+slot)*DM+col]=v;
    } else {
        int e=tid-128, col=h*128+e;
        float k=0.f, vv=0.f;
        const float* p=g_Pk+(size_t)b*3072+col;
        #pragma unroll
        for(int z=0;z<16;z++){ k+=p[1024]; vv+=p[2048]; p+=(size_t)64*3072; }
        kn[e]=k; vn[e]=vv;
        ko[e]= initAll?0.f:g_Kb[(b*MEMN+slot)*DM+col];
        if(initAll){
            #pragma unroll
            for(int m=0;m<MEMN;m++) g_Kb[(b*MEMN+m)*DM+col]=k;
        } else g_Kb[(b*MEMN+slot)*DM+col]=k;
    }
    __syncthreads();
    const int w=tid>>5, lane=tid&31;
    const float sc=0.08838834764831845f;   // 1/sqrt(128)
    float kn0=kn[lane],    kn1=kn[lane+32], kn2=kn[lane+64], kn3=kn[lane+96];
    float ko0=ko[lane],    ko1=ko[lane+32], ko2=ko[lane+64], ko3=ko[lane+96];
    float vn0=vn[lane],    vn1=vn[lane+32], vn2=vn[lane+64], vn3=vn[lane+96];
    float* Srow = g_S + ((size_t)(b*8+h))*16384 + lane;
    #pragma unroll 2
    for(int r=0;r<16;r++){
        const int d=w*16+r;
        float* Sp = Srow + (size_t)d*128;
        const float qnd=qn[d], qod=qo[d];
        float s0,s1,s2,s3;
        if(initAll){
            s0=25.f*qnd*kn0; s1=25.f*qnd*kn1; s2=25.f*qnd*kn2; s3=25.f*qnd*kn3;
        }else{
            s0=Sp[0]  + qnd*kn0 - qod*ko0;
            s1=Sp[32] + qnd*kn1 - qod*ko1;
            s2=Sp[64] + qnd*kn2 - qod*ko2;
            s3=Sp[96] + qnd*kn3 - qod*ko3;
        }
        Sp[0]=s0; Sp[32]=s1; Sp[64]=s2; Sp[96]=s3;
        float mx=fmaxf(fmaxf(s0,s1),fmaxf(s2,s3));
        #pragma unroll
        for(int o=16;o;o>>=1) mx=fmaxf(mx,__shfl_xor_sync(0xffffffffu,mx,o));
        float w0=fexp((s0-mx)*sc), w1=fexp((s1-mx)*sc);
        float w2=fexp((s2-mx)*sc), w3=fexp((s3-mx)*sc);
        float Z  = w0+w1+w2+w3;
        float acc= w0*vn0+w1*vn1+w2*vn2+w3*vn3;
        #pragma unroll
        for(int o=16;o;o>>=1){
            Z  += __shfl_xor_sync(0xffffffffu,Z,o);
            acc+= __shfl_xor_sync(0xffffffffu,acc,o);
        }
        if(lane==0){
            float att=acc/Z;
            g_sync[b*DM + d*8 + h]=att;
            if(outOpt) outOpt[b*DM + d*8 + h]=att;
        }
    }
    __syncthreads();
}

// ======================= the megakernel =====================================
__global__ void __launch_bounds__(256,2) k_mega(
    const float* __restrict__ beff,
    const float* __restrict__ slns, const float* __restrict__ slnb,
    const float* __restrict__ w1, const float* __restrict__ b1,
    const float* __restrict__ w2, const float* __restrict__ b2,
    const float* __restrict__ outw, const float* __restrict__ outb,
    float* __restrict__ out)
{
    __shared__ float sm[6144];
    unsigned target=0;

    // pre-loop: QKV of initial activation (24n x 16z = 384 units), init S + rings
    for(int u=blockIdx.x; u<384; u+=NB)
        unit_gemm2(g_act, g_Wqkv, g_Pk, 3*DM, DM, (u%24)*128, u/24, 4, sm);
    gsync(target);
    for(int u=blockIdx.x; u<512; u+=NB)
        unit_sync(u>>3, u&7, 0, 1, nullptr, sm);
    gsync(target);

    for(int t=0;t<ITERS;t++){
        // P1: cross-Q GEMM (4n x 16z = 64) + output-head GEMM for t-1 (8n x 16z = 128)
        int nU1 = (t==0)?64:192;
        for(int u=blockIdx.x; u<nU1; u+=NB){
            if(u<64) unit_gemm2(g_sync, g_Mq, g_Pq, DI, DM, (u&3)*128, u>>2, 4, sm);
            else { int v=u-64; unit_gemm2(g_sync, outw, g_Po, OUTN, DM, (v&7)*128, v>>3, 4, sm); }
        }
        gsync(target);
        // P2: cross attention (512) + pred for t-1 (64)
        int nU2 = (t==0)?512:576;
        for(int u=blockIdx.x; u<nU2; u+=NB){
            if(u<512) unit_crossatt(u>>3, u&7, beff, g_pre2, sm);
            else unit_pred(u-512, outb, out, t-1, sm);
        }
        gsync(target);
        // P3: synapse GEMM 64x2048x1536 (16n x 16z, K slab 96)
        for(int u=blockIdx.x; u<256; u+=NB)
            unit_gemm2(g_pre2, g_synw2, g_Ps, 2048, 1536, (u&15)*128, u>>4, 6, sm);
        gsync(target);
        // P4: GLU+LN -> trace slot
        for(int u=blockIdx.x; u<64; u+=NB)
            unit_synep(u, slns, slnb, t%MEMN, sm);
        gsync(target);
        // P5: per-neuron NLM
        for(int u=blockIdx.x; u<256; u+=NB)
            unit_nlm(u, w1, b1, w2, b2, t, sm);
        gsync(target);
        // P6: QKV projection of new activation (24n x 16z = 384)
        for(int u=blockIdx.x; u<384; u+=NB)
            unit_gemm2(g_act, g_Wqkv, g_Pk, 3*DM, DM, (u%24)*128, u/24, 4, sm);
        gsync(target);
        // P7: sync attention (coalesced delta update + fused softmax + AV)
        for(int u=blockIdx.x; u<512; u+=NB)
            unit_sync(u>>3, u&7, t%MEMN, 0,
                      (t==ITERS-1)?(out+OFF_SYNC):nullptr, sm);
        gsync(target);
    }
    // tail: output head + pred for tick 49
    for(int u=blockIdx.x; u<128; u+=NB)
        unit_gemm2(g_sync, outw, g_Po, OUTN, DM, (u&7)*128, u>>3, 4, sm);
    gsync(target);
    for(int u=blockIdx.x; u<64; u+=NB)
        unit_pred(u, outb, out, ITERS-1, sm);
}

// ------------------------- host driver -------------------------------------
extern "C" void kernel_launch(void* const* d_in, const int* in_sizes, int n_in,
                              void* d_out, int out_size){
    (void)in_sizes; (void)n_in; (void)out_size;
    const float* x    =(const float*)d_in[0];
    const float* kv_w =(const float*)d_in[1];
    const float* kv_b =(const float*)d_in[2];
    const float* lnks =(const float*)d_in[3];
    const float* lnkb =(const float*)d_in[4];
    const float* q_w  =(const float*)d_in[5];
    const float* q_b  =(const float*)d_in[6];
    const float* inw  =(const float*)d_in[7];
    const float* inb  =(const float*)d_in[8];
    const float* opw  =(const float*)d_in[9];
    const float* opb  =(const float*)d_in[10];
    const float* Wq   =(const float*)d_in[11];
    const float* Wk   =(const float*)d_in[12];
    const float* Wv   =(const float*)d_in[13];
    const float* synw =(const float*)d_in[14];
    const float* synb =(const float*)d_in[15];
    const float* slns =(const float*)d_in[16];
    const float* slnb =(const float*)d_in[17];
    const float* w1   =(const float*)d_in[18];
    const float* b1   =(const float*)d_in[19];
    const float* w2   =(const float*)d_in[20];
    const float* b2   =(const float*)d_in[21];
    const float* sas  =(const float*)d_in[22];
    const float* strc =(const float*)d_in[23];
    const float* outw =(const float*)d_in[24];
    const float* outb =(const float*)d_in[25];
    float* out=(float*)d_out;

    float *p_kv,*p_KV,*p_W,*p_Mq,*p_beff,*p_synw2,*p_bsyn,*p_act,*p_pre2,*p_st;
    unsigned* p_bar;
    cudaGetSymbolAddress((void**)&p_kv,   g_kv);
    cudaGetSymbolAddress((void**)&p_KV,   g_KV);
    cudaGetSymbolAddress((void**)&p_W,    g_Wqkv);
    cudaGetSymbolAddress((void**)&p_Mq,   g_Mq);
    cudaGetSymbolAddress((void**)&p_beff, g_beff);
    cudaGetSymbolAddress((void**)&p_synw2,g_synw2);
    cudaGetSymbolAddress((void**)&p_bsyn, g_bsyn);
    cudaGetSymbolAddress((void**)&p_act,  g_act);
    cudaGetSymbolAddress((void**)&p_pre2, g_pre2);
    cudaGetSymbolAddress((void**)&p_st,   g_st);
    cudaGetSymbolAddress((void**)&p_bar,  g_barCnt);

    // ---- setup: folded weights + KV cache ----
    k_copyW<<<(3*DM*DM+255)/256,256>>>(Wq,Wk,Wv,p_W);
    k_initact<<<(B_*DM+255)/256,256>>>(sas,p_act,p_pre2);
    k_initst<<<(MEMN*DM*B_+255)/256,256>>>(strc,p_st);
    k_gemm<<<dim3(DI/64,MS/64,1),256>>>(x,kv_w,p_KV,nullptr,MS,DI,DI,DI);
    k_lnkv<<<MS,256>>>(p_KV,kv_b,lnks,lnkb,p_kv);
    k_gemm<<<dim3(DM/64,MS/64,1),256>>>(p_kv,inw+(size_t)DI*DI,p_KV,inb+DI,MS,DM,DI,DI);
    k_gemm_tn<<<dim3(DM/64,DI/64),256>>>(inw,q_w,p_Mq,DI,DM,DM,DI,0);
    k_gemm_tn<<<dim3(DI/64,2048/64),256>>>(synw,opw,p_synw2,1536,DI,1536,DI,0);
    k_copyW2<<<(2048*1024+255)/256,256>>>(synw,p_synw2);
    k_bvec<<<2,256>>>(inw,DI,DI,q_b,inb,p_beff,DI);
    k_bvec<<<8,256>>>(synw,1536,DI,opb,synb,p_bsyn,2048);
    // ---- megakernel: all 50 ticks ----
    k_zero<<<1,32>>>(p_bar);
    k_mega<<<NB,256>>>(p_beff,slns,slnb,w1,b1,w2,b2,outw,outb,out);
}

// round 15
// speedup vs baseline: 2.0512x; 1.2696x over previous
#include <cuda_runtime.h>
#include <math.h>

#define B_    64
#define S_    196
#define DM    1024
#define DI    512
#define MEMN  25
#define ITERS 50
#define OUTN  1000
#define MS    (B_*S_)
#define NB    256

#define OFF_CERT (B_*OUTN*ITERS)
#define OFF_SYNC (OFF_CERT + B_*2*ITERS)

// ------------------------- device scratch ----------------------------------
__device__ __align__(16) float g_kv   [MS*DI];
__device__ __align__(16) float g_KV   [MS*DM];
__device__ __align__(16) float g_Wqkv [3*DM*DM];
__device__ __align__(16) float g_Mq   [DI*DM];
__device__ __align__(16) float g_beff [DI];
__device__ __align__(16) float g_synw2[2048*1536];
__device__ __align__(16) float g_bsyn [2048];
__device__ __align__(16) float g_Qb   [B_*MEMN*DM];
__device__ __align__(16) float g_Kb   [B_*MEMN*DM];
__device__ __align__(16) float g_st   [MEMN*DM*B_];
__device__ __align__(16) float g_act  [B_*DM];
__device__ __align__(16) float g_sync [B_*DM];
__device__ __align__(16) float g_pre2 [B_*1536];
__device__ __align__(16) float g_S    [B_*8*128*128];   // cached sync scores
__device__ __align__(16) float g_Pq   [8*B_*DI];
__device__ __align__(16) float g_Po   [8*B_*OUTN];
__device__ __align__(16) float g_Ps   [8*B_*2048];
__device__ __align__(16) float g_Pk   [8*B_*3*DM];
__device__ unsigned g_barCnt;

// ------------------------- fast exp (FMA pipe, not MUFU) -------------------
__device__ __forceinline__ float fexp(float x){
    x = fminf(fmaxf(x,-80.f),80.f);
    float y = x*1.442695041f;
    float n = rintf(y);
    float f = y - n;
    float p = 1.3333558e-3f;
    p = fmaf(p,f,9.6181250e-3f);
    p = fmaf(p,f,5.5504110e-2f);
    p = fmaf(p,f,2.4022650e-1f);
    p = fmaf(p,f,6.9314718e-1f);
    p = fmaf(p,f,1.0f);
    return __int_as_float(__float_as_int(p) + (((int)n)<<23));
}
__device__ __forceinline__ float sigm(float x){ return 1.f/(1.f+fexp(-x)); }

// ------------------------- tf32 mma ----------------------------------------
__device__ __forceinline__ unsigned f2tf(float x){
    unsigned r; asm("cvt.rna.tf32.f32 %0, %1;" : "=r"(r) : "f"(x)); return r;
}
__device__ __forceinline__ void mma_tf32(float* c,
        unsigned a0,unsigned a1,unsigned a2,unsigned a3,
        unsigned b0,unsigned b1){
    asm volatile("mma.sync.aligned.m16n8k8.row.col.f32.tf32.tf32.f32 "
        "{%0,%1,%2,%3}, {%4,%5,%6,%7}, {%8,%9}, {%0,%1,%2,%3};"
        : "+f"(c[0]),"+f"(c[1]),"+f"(c[2]),"+f"(c[3])
        : "r"(a0),"r"(a1),"r"(a2),"r"(a3),"r"(b0),"r"(b1));
}

// ------------------------- reductions --------------------------------------
__device__ __forceinline__ float warpSum(float v){
    #pragma unroll
    for(int o=16;o;o>>=1) v += __shfl_down_sync(0xffffffffu,v,o);
    return v;
}
__device__ __forceinline__ float warpMax(float v){
    #pragma unroll
    for(int o=16;o;o>>=1) v = fmaxf(v,__shfl_down_sync(0xffffffffu,v,o));
    return v;
}
__device__ float blockSum(float v, float* buf){
    int lane=threadIdx.x&31, w=threadIdx.x>>5, nw=(blockDim.x+31)>>5;
    v=warpSum(v);
    if(lane==0) buf[w]=v;
    __syncthreads();
    v=(threadIdx.x<nw)?buf[threadIdx.x]:0.f;
    if(w==0) v=warpSum(v);
    if(threadIdx.x==0) buf[0]=v;
    __syncthreads();
    float r=buf[0]; __syncthreads(); return r;
}
__device__ float blockMax(float v, float* buf){
    int lane=threadIdx.x&31, w=threadIdx.x>>5, nw=(blockDim.x+31)>>5;
    v=warpMax(v);
    if(lane==0) buf[w]=v;
    __syncthreads();
    v=(threadIdx.x<nw)?buf[threadIdx.x]:-1e30f;
    if(w==0) v=warpMax(v);
    if(threadIdx.x==0) buf[0]=v;
    __syncthreads();
    float r=buf[0]; __syncthreads(); return r;
}

// ------------------------- grid barrier ------------------------------------
__device__ __forceinline__ void gsync(unsigned &target){
    __threadfence();
    __syncthreads();
    target += NB;
    if(threadIdx.x==0){
        atomicAdd(&g_barCnt,1u);
        while(*(volatile unsigned*)&g_barCnt < target) __nanosleep(64);
        __threadfence();
    }
    __syncthreads();
}

// ======================= tf32 GEMM unit =====================================
// A: 64 x Ksrc rm. W: N x Ksrc rm (i.e. computes A @ W^T).
// Computes 64x128 output tile at cols [n0,n0+128) over K-slab z (ksteps*16).
// Writes P[(z*64+m)*N + n]  (+bias if given).
#define AS_STRIDE 68
#define BS_STRIDE 132
__device__ void unit_gemm_tc(const float* __restrict__ A,const float* __restrict__ W,
                             float* __restrict__ P,const float* __restrict__ bias,
                             int N,int Ksrc,int n0,int z,int ksteps,float* sm){
    float* As=sm;            // 2 x 16 x 68
    float* Bs=sm+2176;       // 2 x 16 x 132
    const int tid=threadIdx.x;
    const int ar=tid>>2, ac=(tid&3)*4;
    const int br=tid>>1, bc=(tid&1)*8;
    const int k0=z*ksteps*16;
    const bool wok=(n0+br)<N;
    const float* Ap=A+(size_t)ar*Ksrc + k0 + ac;
    const float* Wp=W+(size_t)(n0+br)*Ksrc + k0 + bc;
    const int w=tid>>5, lane=tid&31;
    const int mw=(w&1)*32, nw=(w>>1)*32;
    const int gid=lane>>2, tg=lane&3;
    float c[2][4][4];
    #pragma unroll
    for(int i=0;i<2;i++)
        #pragma unroll
        for(int j=0;j<4;j++){c[i][j][0]=0;c[i][j][1]=0;c[i][j][2]=0;c[i][j][3]=0;}
    float4 a=*(const float4*)Ap;
    float4 b0v=wok?*(const float4*)Wp:make_float4(0,0,0,0);
    float4 b1v=wok?*(const float4*)(Wp+4):make_float4(0,0,0,0);
    __syncthreads();                     // drain previous unit's smem use
    for(int s=0;s<ksteps;s++){
        float* Ab=As+(s&1)*1088;
        float* Bb=Bs+(s&1)*2112;
        Ab[(ac+0)*AS_STRIDE+ar]=__uint_as_float(f2tf(a.x));
        Ab[(ac+1)*AS_STRIDE+ar]=__uint_as_float(f2tf(a.y));
        Ab[(ac+2)*AS_STRIDE+ar]=__uint_as_float(f2tf(a.z));
        Ab[(ac+3)*AS_STRIDE+ar]=__uint_as_float(f2tf(a.w));
        Bb[(bc+0)*BS_STRIDE+br]=__uint_as_float(f2tf(b0v.x));
        Bb[(bc+1)*BS_STRIDE+br]=__uint_as_float(f2tf(b0v.y));
        Bb[(bc+2)*BS_STRIDE+br]=__uint_as_float(f2tf(b0v.z));
        Bb[(bc+3)*BS_STRIDE+br]=__uint_as_float(f2tf(b0v.w));
        Bb[(bc+4)*BS_STRIDE+br]=__uint_as_float(f2tf(b1v.x));
        Bb[(bc+5)*BS_STRIDE+br]=__uint_as_float(f2tf(b1v.y));
        Bb[(bc+6)*BS_STRIDE+br]=__uint_as_float(f2tf(b1v.z));
        Bb[(bc+7)*BS_STRIDE+br]=__uint_as_float(f2tf(b1v.w));
        __syncthreads();
        if(s+1<ksteps){
            a=*(const float4*)(Ap+(s+1)*16);
            b0v=wok?*(const float4*)(Wp+(s+1)*16):make_float4(0,0,0,0);
            b1v=wok?*(const float4*)(Wp+(s+1)*16+4):make_float4(0,0,0,0);
        }
        #pragma unroll
        for(int kb=0;kb<16;kb+=8){
            unsigned af[2][4];
            #pragma unroll
            for(int mf=0;mf<2;mf++){
                int mb=mw+mf*16;
                af[mf][0]=__float_as_uint(Ab[(kb+tg  )*AS_STRIDE + mb+gid  ]);
                af[mf][1]=__float_as_uint(Ab[(kb+tg  )*AS_STRIDE + mb+gid+8]);
                af[mf][2]=__float_as_uint(Ab[(kb+tg+4)*AS_STRIDE + mb+gid  ]);
                af[mf][3]=__float_as_uint(Ab[(kb+tg+4)*AS_STRIDE + mb+gid+8]);
            }
            #pragma unroll
            for(int nf=0;nf<4;nf++){
                int nb=nw+nf*8;
                unsigned bf0=__float_as_uint(Bb[(kb+tg  )*BS_STRIDE + nb+gid]);
                unsigned bf1=__float_as_uint(Bb[(kb+tg+4)*BS_STRIDE + nb+gid]);
                mma_tf32(c[0][nf],af[0][0],af[0][1],af[0][2],af[0][3],bf0,bf1);
                mma_tf32(c[1][nf],af[1][0],af[1][1],af[1][2],af[1][3],bf0,bf1);
            }
        }
        __syncthreads();
    }
    float* Pb=P+((size_t)z*64)*N + n0;
    #pragma unroll
    for(int mf=0;mf<2;mf++){
        #pragma unroll
        for(int nf=0;nf<4;nf++){
            int m0r=mw+mf*16+gid;
            int nn=nw+nf*8+tg*2;
            float v0=c[mf][nf][0],v1=c[mf][nf][1],v2=c[mf][nf][2],v3=c[mf][nf][3];
            if(bias && n0+nn<N){ v0+=bias[n0+nn]; v2+=bias[n0+nn]; }
            if(bias && n0+nn+1<N){ v1+=bias[n0+nn+1]; v3+=bias[n0+nn+1]; }
            if(n0+nn<N){
                Pb[(size_t)m0r*N+nn]=v0;
                Pb[(size_t)(m0r+8)*N+nn]=v2;
            }
            if(n0+nn+1<N){
                Pb[(size_t)m0r*N+nn+1]=v1;
                Pb[(size_t)(m0r+8)*N+nn+1]=v3;
            }
        }
    }
}

// standalone wrapper for the big setup GEMMs (M multiple of 64)
__global__ void __launch_bounds__(256) k_gemm_tc(const float* __restrict__ A,
                                                 const float* __restrict__ W,
                                                 float* __restrict__ C,
                                                 const float* __restrict__ bias,
                                                 int N,int K){
    __shared__ float sm[6400];
    unit_gemm_tc(A + (size_t)blockIdx.y*64*K, W,
                 C + (size_t)blockIdx.y*64*N, bias,
                 N, K, blockIdx.x*128, 0, K/16, sm);
}

// ------------------------- setup: TN GEMM C = A(MxK)@B(KxN), fp32 ----------
__global__ void __launch_bounds__(256) k_gemm_tn(const float* __restrict__ A,
                                                 const float* __restrict__ B,
                                                 float* __restrict__ C,
                                                 int lda,int ldb,int ldc,int K,int transC){
    __shared__ float As[16][64];
    __shared__ float Bs[16][64];
    const int n0=blockIdx.x*64, m0=blockIdx.y*64;
    const int tid=threadIdx.x;
    const int tx=tid&15, ty=tid>>4;
    const int lr=tid>>2, lc=tid&3;
    const int br=tid>>4, bc=(tid&15)*4;
    float c[4][4];
    #pragma unroll
    for(int i=0;i<4;i++){c[i][0]=0;c[i][1]=0;c[i][2]=0;c[i][3]=0;}
    for(int k0=0;k0<K;k0+=16){
        float4 av=*(const float4*)(A+(size_t)(m0+lr)*lda + k0 + lc*4);
        float4 bv=*(const float4*)(B+(size_t)(k0+br)*ldb + n0 + bc);
        __syncthreads();
        As[lc*4+0][lr]=av.x; As[lc*4+1][lr]=av.y; As[lc*4+2][lr]=av.z; As[lc*4+3][lr]=av.w;
        *(float4*)&Bs[br][bc]=bv;
        __syncthreads();
        #pragma unroll
        for(int q=0;q<16;q++){
            float4 a=*(const float4*)&As[q][ty*4];
            float4 w=*(const float4*)&Bs[q][tx*4];
            c[0][0]+=a.x*w.x; c[0][1]+=a.x*w.y; c[0][2]+=a.x*w.z; c[0][3]+=a.x*w.w;
            c[1][0]+=a.y*w.x; c[1][1]+=a.y*w.y; c[1][2]+=a.y*w.z; c[1][3]+=a.y*w.w;
            c[2][0]+=a.z*w.x; c[2][1]+=a.z*w.y; c[2][2]+=a.z*w.z; c[2][3]+=a.z*w.w;
            c[3][0]+=a.w*w.x; c[3][1]+=a.w*w.y; c[3][2]+=a.w*w.z; c[3][3]+=a.w*w.w;
        }
    }
    #pragma unroll
    for(int i=0;i<4;i++){
        #pragma unroll
        for(int j=0;j<4;j++){
            int m=m0+ty*4+i, n=n0+tx*4+j;
            if(transC) C[(size_t)n*ldc+m]=c[i][j];
            else       C[(size_t)m*ldc+n]=c[i][j];
        }
    }
}

// ------------------------- setup small kernels ------------------------------
__global__ void k_copyW(const float* __restrict__ wq,const float* __restrict__ wk,
                        const float* __restrict__ wv,float* __restrict__ dst){
    int i=blockIdx.x*blockDim.x+threadIdx.x;
    if(i>=3*DM*DM) return;
    int part=i/(DM*DM), r=i%(DM*DM);
    dst[i]=(part==0)?wq[r]:(part==1)?wk[r]:wv[r];
}
__global__ void k_copyW2(const float* __restrict__ synw,float* __restrict__ dst){
    int i=blockIdx.x*blockDim.x+threadIdx.x;
    if(i>=2048*1024) return;
    int m=i>>10, k=i&1023;
    dst[(size_t)m*1536+512+k]=synw[(size_t)m*1536+512+k];
}
__global__ void k_initact(const float* __restrict__ sas,float* __restrict__ act,
                          float* __restrict__ pre2){
    int i=blockIdx.x*blockDim.x+threadIdx.x;
    if(i>=B_*DM) return;
    float v=sas[i&(DM-1)];
    act[i]=v;
    pre2[(size_t)(i>>10)*1536 + 512 + (i&(DM-1))]=v;
}
__global__ void k_initst(const float* __restrict__ strace,float* __restrict__ st){
    int i=blockIdx.x*blockDim.x+threadIdx.x;
    if(i>=MEMN*DM*B_) return;
    int slot=i/(DM*B_), r=i%(DM*B_), d=r/B_;
    st[i]=strace[d*MEMN+slot];
}
__global__ void k_lnkv(const float* __restrict__ tmp,const float* __restrict__ kvb,
                       const float* __restrict__ lns,const float* __restrict__ lnb,
                       float* __restrict__ kv){
    __shared__ float red[33];
    int r=blockIdx.x, tid=threadIdx.x;
    float v0=tmp[r*DI+tid]+kvb[tid];
    float v1=tmp[r*DI+tid+256]+kvb[tid+256];
    float s=blockSum(v0+v1,red);
    float sq=blockSum(v0*v0+v1*v1,red);
    float mean=s*(1.f/DI);
    float var=sq*(1.f/DI)-mean*mean;
    float rstd=rsqrtf(var+1e-5f);
    kv[r*DI+tid]    =(v0-mean)*rstd*lns[tid]    +lnb[tid];
    kv[r*DI+tid+256]=(v1-mean)*rstd*lns[tid+256]+lnb[tid+256];
}
__global__ void k_bvec(const float* __restrict__ W,int lda,int K,
                       const float* __restrict__ v,const float* __restrict__ b0,
                       float* __restrict__ o,int n){
    int i=blockIdx.x*blockDim.x+threadIdx.x;
    if(i>=n) return;
    float a=b0[i];
    const float* wr=W+(size_t)i*lda;
    for(int k=0;k<K;k++) a+=wr[k]*v[k];
    o[i]=a;
}
__global__ void k_zero(unsigned* p){ if(threadIdx.x==0) *p=0; }

// ======================= other megakernel phase workers =====================
__device__ void unit_crossatt(int b,int h,const float* __restrict__ beff,
                              float* __restrict__ pre2,float* sm){
    float* q2s=sm;          // 64
    float* ws =sm+64;       // 196
    float* os =sm+260;      // 256
    float* red=sm+520;      // 33
    const int tid=threadIdx.x;
    __syncthreads();
    if(tid<64){
        float a=beff[h*64+tid];
        #pragma unroll
        for(int z=0;z<8;z++) a+=g_Pq[((size_t)z*64+b)*DI + h*64+tid];
        q2s[tid]=a;
    }
    __syncthreads();
    float sv=-1e30f;
    if(tid<S_){
        const float* kr=g_KV+((size_t)(b*S_+tid))*DM + h*64;
        float a=0.f;
        #pragma unroll 8
        for(int dd=0;dd<64;dd++) a+=q2s[dd]*kr[dd];
        sv=a*0.125f;
    }
    float mxv=blockMax(sv,red);
    float ev=(tid<S_)?fexp(sv-mxv):0.f;
    float Z=blockSum(ev,red);
    if(tid<S_) ws[tid]=ev/Z;
    __syncthreads();
    int dd=tid&63, part=tid>>6;
    float acc=0.f;
    for(int s=part*49;s<part*49+49;s++)
        acc+=ws[s]*g_KV[((size_t)(b*S_+s))*DM + DI + h*64 + dd];
    os[part*64+dd]=acc;
    __syncthreads();
    if(tid<64)
        pre2[(size_t)b*1536 + h*64 + tid]=os[tid]+os[64+tid]+os[128+tid]+os[192+tid];
}

__device__ void unit_pred(int b,const float* __restrict__ ob,
                          float* __restrict__ out,int t,float* sm){
    float* pv=sm;           // 1000
    float* red=sm+1000;     // 33
    const int tid=threadIdx.x;
    __syncthreads();
    float lmax=-1e30f;
    for(int j=tid;j<OUTN;j+=256){
        float v=ob[j];
        const float* p=g_Po+(size_t)b*OUTN + j;
        #pragma unroll
        for(int z=0;z<8;z++){ v+=p[0]; p+=(size_t)64*OUTN; }
        pv[j]=v;
        out[((size_t)b*OUTN+j)*ITERS+t]=v;
        lmax=fmaxf(lmax,v);
    }
    float mx=blockMax(lmax,red);
    float lz=0.f, ls1=0.f;
    for(int j=tid;j<OUTN;j+=256){
        float e=fexp(pv[j]-mx);
        lz+=e; ls1+=e*pv[j];
    }
    float Z=blockSum(lz,red);
    float S1=blockSum(ls1,red);
    if(tid==0){
        float logZ=logf(Z);
        float plogp=S1/Z - mx - logZ;
        float ne=-plogp*(1.f/logf((float)OUTN));
        out[OFF_CERT + ((size_t)b*2+0)*ITERS + t]=ne;
        out[OFF_CERT + ((size_t)b*2+1)*ITERS + t]=1.f-ne;
    }
}

__device__ void unit_synep(int b,const float* __restrict__ lns,
                           const float* __restrict__ lnb,int w,float* sm){
    float* vals=sm;         // 1024
    float* red=sm+1024;     // 33
    const int tid=threadIdx.x;
    __syncthreads();
    float s=0.f, sq=0.f;
    #pragma unroll
    for(int r=0;r<4;r++){
        int j=tid+r*256;
        float a=g_bsyn[j], g=g_bsyn[DM+j];
        const float* p=g_Ps+(size_t)b*2048 + j;
        #pragma unroll
        for(int z=0;z<8;z++){
            a+=p[0]; g+=p[DM];
            p+=(size_t)64*2048;
        }
        float v=a*sigm(g);
        vals[j]=v; s+=v; sq+=v*v;
    }
    s=blockSum(s,red); sq=blockSum(sq,red);
    float mean=s*(1.f/DM);
    float var=sq*(1.f/DM)-mean*mean;
    float rstd=rsqrtf(var+1e-5f);
    #pragma unroll
    for(int r=0;r<4;r++){
        int j=tid+r*256;
        g_st[((size_t)w*DM + j)*B_ + b]=(vals[j]-mean)*rstd*lns[j]+lnb[j];
    }
}

__device__ void unit_nlm(int u,const float* __restrict__ w1,const float* __restrict__ b1,
                         const float* __restrict__ w2,const float* __restrict__ b2,
                         int t,float* sm){
    float* w1s=sm;          // 3200
    float* b1s=sm+3200;     // 128
    float* w2s=sm+3328;     // 128
    float* b2s=sm+3456;     // 8
    const int tid=threadIdx.x, d0=u*4;
    __syncthreads();
    for(int i=tid;i<MEMN*32*4;i+=256){
        int m=i>>7, r=i&127, j=r>>2, dl=r&3;
        w1s[i]=w1[(size_t)(m*32+j)*DM + d0+dl];
    }
    if(tid<128){ int j=tid>>2, dl=tid&3; b1s[tid]=b1[(d0+dl)*32+j]; }
    else {
        int i=tid-128; int hh=i>>3, o=(i>>2)&1, dl=i&3;
        w2s[i]=w2[(size_t)(hh*2+o)*DM + d0+dl];
    }
    if(tid<8){ int o=tid>>2, dl=tid&3; b2s[tid]=b2[(d0+dl)*2+o]; }
    __syncthreads();
    int b=tid&63, dl=tid>>6, d=d0+dl;
    float stv[MEMN];
    #pragma unroll
    for(int m=0;m<MEMN;m++){
        int phys=(t+1+m)%MEMN;
        stv[m]=g_st[((size_t)phys*DM + d)*B_ + b];
    }
    float o0=0.f,o1=0.f;
    #pragma unroll
    for(int j=0;j<16;j++){
        float a=b1s[j*4+dl], g=b1s[(j+16)*4+dl];
        #pragma unroll
        for(int m=0;m<MEMN;m++){
            a+=stv[m]*w1s[(m*32+j)*4+dl];
            g+=stv[m]*w1s[(m*32+j+16)*4+dl];
        }
        float hv=a*sigm(g);
        o0+=hv*w2s[(j*2+0)*4+dl];
        o1+=hv*w2s[(j*2+1)*4+dl];
    }
    o0+=b2s[0*4+dl]; o1+=b2s[1*4+dl];
    float v=o0*sigm(o1);
    g_act[b*DM+d]=v;
    g_pre2[(size_t)b*1536 + 512 + d]=v;
}

// sync attention: cached score matrix, rank-1 delta update, fused softmax+AV.
__device__ void unit_sync(int b,int h,int slot,int initAll,
                          float* __restrict__ outOpt,float* sm){
    float* qn=sm;           // 128
    float* kn=sm+128;       // 128
    float* vn=sm+256;       // 128
    float* qo=sm+384;       // 128
    float* ko=sm+512;       // 128
    const int tid=threadIdx.x;
    __syncthreads();
    if(tid<128){
        int col=h*128+tid;
        float v=0.f;
        const float* p=g_Pk+(size_t)b*3072+col;
        #pragma unroll
        for(int z=0;z<8;z++){ v+=*p; p+=(size_t)64*3072; }
        qn[tid]=v;
        qo[tid]= initAll?0.f:g_Qb[(b*MEMN+slot)*DM+col];
        if(initAll){
            #pragma unroll
            for(int m=0;m<MEMN;m++) g_Qb[(b*MEMN+m)*DM+col]=v;
        } else g_Qb[(b*MEMN+slot)*DM+col]=v;
    } else {
        int e=tid-128, col=h*128+e;
        float k=0.f, vv=0.f;
        const float* p=g_Pk+(size_t)b*3072+col;
        #pragma unroll
        for(int z=0;z<8;z++){ k+=p[1024]; vv+=p[2048]; p+=(size_t)64*3072; }
        kn[e]=k; vn[e]=vv;
        ko[e]= initAll?0.f:g_Kb[(b*MEMN+slot)*DM+col];
        if(initAll){
            #pragma unroll
            for(int m=0;m<MEMN;m++) g_Kb[(b*MEMN+m)*DM+col]=k;
        } else g_Kb[(b*MEMN+slot)*DM+col]=k;
    }
    __syncthreads();
    const int w=tid>>5, lane=tid&31;
    const float sc=0.08838834764831845f;   // 1/sqrt(128)
    float kn0=kn[lane],    kn1=kn[lane+32], kn2=kn[lane+64], kn3=kn[lane+96];
    float ko0=ko[lane],    ko1=ko[lane+32], ko2=ko[lane+64], ko3=ko[lane+96];
    float vn0=vn[lane],    vn1=vn[lane+32], vn2=vn[lane+64], vn3=vn[lane+96];
    float* Srow = g_S + ((size_t)(b*8+h))*16384 + lane;
    #pragma unroll 2
    for(int r=0;r<16;r++){
        const int d=w*16+r;
        float* Sp = Srow + (size_t)d*128;
        const float qnd=qn[d], qod=qo[d];
        float s0,s1,s2,s3;
        if(initAll){
            s0=25.f*qnd*kn0; s1=25.f*qnd*kn1; s2=25.f*qnd*kn2; s3=25.f*qnd*kn3;
        }else{
            s0=Sp[0]  + qnd*kn0 - qod*ko0;
            s1=Sp[32] + qnd*kn1 - qod*ko1;
            s2=Sp[64] + qnd*kn2 - qod*ko2;
            s3=Sp[96] + qnd*kn3 - qod*ko3;
        }
        Sp[0]=s0; Sp[32]=s1; Sp[64]=s2; Sp[96]=s3;
        float mx=fmaxf(fmaxf(s0,s1),fmaxf(s2,s3));
        #pragma unroll
        for(int o=16;o;o>>=1) mx=fmaxf(mx,__shfl_xor_sync(0xffffffffu,mx,o));
        float w0=fexp((s0-mx)*sc), w1=fexp((s1-mx)*sc);
        float w2=fexp((s2-mx)*sc), w3=fexp((s3-mx)*sc);
        float Z  = w0+w1+w2+w3;
        float acc= w0*vn0+w1*vn1+w2*vn2+w3*vn3;
        #pragma unroll
        for(int o=16;o;o>>=1){
            Z  += __shfl_xor_sync(0xffffffffu,Z,o);
            acc+= __shfl_xor_sync(0xffffffffu,acc,o);
        }
        if(lane==0){
            float att=acc/Z;
            g_sync[b*DM + d*8 + h]=att;
            if(outOpt) outOpt[b*DM + d*8 + h]=att;
        }
    }
    __syncthreads();
}

// ======================= the megakernel =====================================
__global__ void __launch_bounds__(256,2) k_mega(
    const float* __restrict__ beff,
    const float* __restrict__ slns, const float* __restrict__ slnb,
    const float* __restrict__ w1, const float* __restrict__ b1,
    const float* __restrict__ w2, const float* __restrict__ b2,
    const float* __restrict__ outw, const float* __restrict__ outb,
    float* __restrict__ out)
{
    __shared__ float sm[6400];
    unsigned target=0;

    // pre-loop: QKV of initial activation (24n x 8z = 192 units), init S + rings
    for(int u=blockIdx.x; u<192; u+=NB)
        unit_gemm_tc(g_act, g_Wqkv, g_Pk, nullptr, 3*DM, DM, (u%24)*128, u/24, 8, sm);
    gsync(target);
    for(int u=blockIdx.x; u<512; u+=NB)
        unit_sync(u>>3, u&7, 0, 1, nullptr, sm);
    gsync(target);

    for(int t=0;t<ITERS;t++){
        // P1: cross-Q GEMM (4n x 8z = 32) + output-head GEMM for t-1 (8n x 8z = 64)
        int nU1 = (t==0)?32:96;
        for(int u=blockIdx.x; u<nU1; u+=NB){
            if(u<32) unit_gemm_tc(g_sync, g_Mq, g_Pq, nullptr, DI, DM, (u&3)*128, u>>2, 8, sm);
            else { int v=u-32; unit_gemm_tc(g_sync, outw, g_Po, nullptr, OUTN, DM, (v&7)*128, v>>3, 8, sm); }
        }
        gsync(target);
        // P2: cross attention (512) + pred for t-1 (64)
        int nU2 = (t==0)?512:576;
        for(int u=blockIdx.x; u<nU2; u+=NB){
            if(u<512) unit_crossatt(u>>3, u&7, beff, g_pre2, sm);
            else unit_pred(u-512, outb, out, t-1, sm);
        }
        gsync(target);
        // P3: synapse GEMM 64x2048x1536 (16n x 8z, K slab 192)
        for(int u=blockIdx.x; u<128; u+=NB)
            unit_gemm_tc(g_pre2, g_synw2, g_Ps, nullptr, 2048, 1536, (u&15)*128, u>>4, 12, sm);
        gsync(target);
        // P4: GLU+LN -> trace slot
        for(int u=blockIdx.x; u<64; u+=NB)
            unit_synep(u, slns, slnb, t%MEMN, sm);
        gsync(target);
        // P5: per-neuron NLM
        for(int u=blockIdx.x; u<256; u+=NB)
            unit_nlm(u, w1, b1, w2, b2, t, sm);
        gsync(target);
        // P6: QKV projection of new activation (24n x 8z = 192)
        for(int u=blockIdx.x; u<192; u+=NB)
            unit_gemm_tc(g_act, g_Wqkv, g_Pk, nullptr, 3*DM, DM, (u%24)*128, u/24, 8, sm);
        gsync(target);
        // P7: sync attention (delta update + fused softmax + AV)
        for(int u=blockIdx.x; u<512; u+=NB)
            unit_sync(u>>3, u&7, t%MEMN, 0,
                      (t==ITERS-1)?(out+OFF_SYNC):nullptr, sm);
        gsync(target);
    }
    // tail: output head + pred for tick 49
    for(int u=blockIdx.x; u<64; u+=NB)
        unit_gemm_tc(g_sync, outw, g_Po, nullptr, OUTN, DM, (u&7)*128, u>>3, 8, sm);
    gsync(target);
    for(int u=blockIdx.x; u<64; u+=NB)
        unit_pred(u, outb, out, ITERS-1, sm);
}

// ------------------------- host driver -------------------------------------
extern "C" void kernel_launch(void* const* d_in, const int* in_sizes, int n_in,
                              void* d_out, int out_size){
    (void)in_sizes; (void)n_in; (void)out_size;
    const float* x    =(const float*)d_in[0];
    const float* kv_w =(const float*)d_in[1];
    const float* kv_b =(const float*)d_in[2];
    const float* lnks =(const float*)d_in[3];
    const float* lnkb =(const float*)d_in[4];
    const float* q_w  =(const float*)d_in[5];
    const float* q_b  =(const float*)d_in[6];
    const float* inw  =(const float*)d_in[7];
    const float* inb  =(const float*)d_in[8];
    const float* opw  =(const float*)d_in[9];
    const float* opb  =(const float*)d_in[10];
    const float* Wq   =(const float*)d_in[11];
    const float* Wk   =(const float*)d_in[12];
    const float* Wv   =(const float*)d_in[13];
    const float* synw =(const float*)d_in[14];
    const float* synb =(const float*)d_in[15];
    const float* slns =(const float*)d_in[16];
    const float* slnb =(const float*)d_in[17];
    const float* w1   =(const float*)d_in[18];
    const float* b1   =(const float*)d_in[19];
    const float* w2   =(const float*)d_in[20];
    const float* b2   =(const float*)d_in[21];
    const float* sas  =(const float*)d_in[22];
    const float* strc =(const float*)d_in[23];
    const float* outw =(const float*)d_in[24];
    const float* outb =(const float*)d_in[25];
    float* out=(float*)d_out;

    float *p_kv,*p_KV,*p_W,*p_Mq,*p_beff,*p_synw2,*p_bsyn,*p_act,*p_pre2,*p_st;
    unsigned* p_bar;
    cudaGetSymbolAddress((void**)&p_kv,   g_kv);
    cudaGetSymbolAddress((void**)&p_KV,   g_KV);
    cudaGetSymbolAddress((void**)&p_W,    g_Wqkv);
    cudaGetSymbolAddress((void**)&p_Mq,   g_Mq);
    cudaGetSymbolAddress((void**)&p_beff, g_beff);
    cudaGetSymbolAddress((void**)&p_synw2,g_synw2);
    cudaGetSymbolAddress((void**)&p_bsyn, g_bsyn);
    cudaGetSymbolAddress((void**)&p_act,  g_act);
    cudaGetSymbolAddress((void**)&p_pre2, g_pre2);
    cudaGetSymbolAddress((void**)&p_st,   g_st);
    cudaGetSymbolAddress((void**)&p_bar,  g_barCnt);

    // ---- setup: folded weights + KV cache (big GEMMs via tf32 tensor cores) ----
    k_copyW<<<(3*DM*DM+255)/256,256>>>(Wq,Wk,Wv,p_W);
    k_initact<<<(B_*DM+255)/256,256>>>(sas,p_act,p_pre2);
    k_initst<<<(MEMN*DM*B_+255)/256,256>>>(strc,p_st);
    k_gemm_tc<<<dim3(DI/128,MS/64),256>>>(x,kv_w,p_KV,nullptr,DI,DI);
    k_lnkv<<<MS,256>>>(p_KV,kv_b,lnks,lnkb,p_kv);
    k_gemm_tc<<<dim3(DM/128,MS/64),256>>>(p_kv,inw+(size_t)DI*DI,p_KV,inb+DI,DM,DI);
    k_gemm_tn<<<dim3(DM/64,DI/64),256>>>(inw,q_w,p_Mq,DI,DM,DM,DI,0);
    k_gemm_tn<<<dim3(DI/64,2048/64),256>>>(synw,opw,p_synw2,1536,DI,1536,DI,0);
    k_copyW2<<<(2048*1024+255)/256,256>>>(synw,p_synw2);
    k_bvec<<<2,256>>>(inw,DI,DI,q_b,inb,p_beff,DI);
    k_bvec<<<8,256>>>(synw,1536,DI,opb,synb,p_bsyn,2048);
    // ---- megakernel: all 50 ticks ----
    k_zero<<<1,32>>>(p_bar);
    k_mega<<<NB,256>>>(p_beff,slns,slnb,w1,b1,w2,b2,outw,outb,out);
}